// round 4
// baseline (speedup 1.0000x reference)
#include <cuda_runtime.h>
#include <cstdint>
#include <cstddef>

#define N_NODES 100000
#define N_EDGES 1600000
#define NREG    50000
#define D       128
#define NP      4
#define NL      2

// ---------------- scratch (device globals; no allocations allowed) ----------
__device__ float g_x0[(size_t)N_NODES * D];          // 51.2 MB
__device__ float g_x1[(size_t)N_NODES * D];          // 51.2 MB
__device__ float g_agg[(size_t)N_NODES * D];         // 51.2 MB
__device__ float g_cnt[N_NODES];
__device__ float g_sems[(size_t)NP * NREG * D];      // 102.4 MB, layout [p][n][d]
__device__ float g_query[NP * D];

// ---------------- gather: x[n] = E[eids[n]] --------------------------------
__global__ void gather_kernel(const float* __restrict__ E,
                              const int* __restrict__ eids,
                              float* __restrict__ x) {
    int i = blockIdx.x * blockDim.x + threadIdx.x;       // over N_NODES*32 float4
    if (i >= N_NODES * (D / 4)) return;
    int n = i >> 5;
    int c = i & 31;
    int e = eids[n];
    reinterpret_cast<float4*>(x)[(size_t)n * 32 + c] =
        reinterpret_cast<const float4*>(E)[(size_t)e * 32 + c];
}

// ---------------- scatter-add: agg[dst] += x[src], cnt[dst] += 1 -----------
// one warp per edge; lane handles one float4 (16B) -> vector REDG.128
__global__ void scatter_kernel(const float* __restrict__ x,
                               const int* __restrict__ src,
                               const int* __restrict__ dst,
                               float* __restrict__ agg,
                               float* __restrict__ cnt) {
    int warp = (blockIdx.x * blockDim.x + threadIdx.x) >> 5;
    int lane = threadIdx.x & 31;
    if (warp >= N_EDGES) return;
    int s = src[warp];
    int d = dst[warp];
    float4 v = reinterpret_cast<const float4*>(x)[(size_t)s * 32 + lane];
    float* a = agg + (size_t)d * D + lane * 4;
    asm volatile("red.global.add.v4.f32 [%0], {%1,%2,%3,%4};"
                 :: "l"(a), "f"(v.x), "f"(v.y), "f"(v.z), "f"(v.w)
                 : "memory");
    if (lane == 0) atomicAdd(cnt + d, 1.0f);
}

// ---------------- fused RGCN GEMM ------------------------------------------
// out = relu( (agg/max(cnt,1)) @ Wm  +  x @ Wr  + bias )
// treated as [A_norm | x] (K=256) @ [Wm ; Wr] (256x128)
#define BM 128
#define BN 128
#define BK 16

__global__ __launch_bounds__(256)
void rgcn_gemm_kernel(const float* __restrict__ agg,
                      const float* __restrict__ cnt,
                      const float* __restrict__ x,
                      const float* __restrict__ Wm,   // message weight (W_rel)
                      const float* __restrict__ Wr,   // root weight (W_root)
                      const float* __restrict__ bias,
                      float* __restrict__ out) {
    __shared__ float As[BK][BM + 4];
    __shared__ float Bs[BK][BN];

    int row0 = blockIdx.x * BM;
    int t  = threadIdx.x;
    int ty = t >> 4;          // 0..15
    int tx = t & 15;          // 0..15

    float acc[8][8];
    #pragma unroll
    for (int i = 0; i < 8; i++)
        #pragma unroll
        for (int j = 0; j < 8; j++) acc[i][j] = 0.0f;

    int la_row = t >> 2;          // 0..63
    int la_k4  = (t & 3) * 4;     // 0,4,8,12

    #pragma unroll 1
    for (int kt = 0; kt < 256 / BK; kt++) {
        int k0 = kt * BK;
        // ---- load A tile (128 rows x 16 k), normalized on the fly ----
        #pragma unroll
        for (int h = 0; h < 2; h++) {
            int row = row0 + la_row + h * 64;
            float4 v = make_float4(0.f, 0.f, 0.f, 0.f);
            if (row < N_NODES) {
                int kk = k0 + la_k4;
                if (kk < 128) {
                    float rinv = 1.0f / fmaxf(cnt[row], 1.0f);
                    v = *reinterpret_cast<const float4*>(agg + (size_t)row * D + kk);
                    v.x *= rinv; v.y *= rinv; v.z *= rinv; v.w *= rinv;
                } else {
                    v = *reinterpret_cast<const float4*>(x + (size_t)row * D + (kk - 128));
                }
            }
            As[la_k4 + 0][la_row + h * 64] = v.x;
            As[la_k4 + 1][la_row + h * 64] = v.y;
            As[la_k4 + 2][la_row + h * 64] = v.z;
            As[la_k4 + 3][la_row + h * 64] = v.w;
        }
        // ---- load B tile (16 k x 128 n) ----
        #pragma unroll
        for (int h = 0; h < 2; h++) {
            int s  = t + h * 256;          // 0..511 float4 slots
            int kB = s >> 5;               // 0..15
            int n4 = (s & 31) * 4;         // 0..124
            int kk = k0 + kB;
            const float* W = (kk < 128)
                ? (Wm + (size_t)kk * 128 + n4)
                : (Wr + (size_t)(kk - 128) * 128 + n4);
            *reinterpret_cast<float4*>(&Bs[kB][n4]) =
                *reinterpret_cast<const float4*>(W);
        }
        __syncthreads();

        #pragma unroll
        for (int kk = 0; kk < BK; kk++) {
            float a[8], bb[8];
            *reinterpret_cast<float4*>(a)      = *reinterpret_cast<float4*>(&As[kk][ty * 8]);
            *reinterpret_cast<float4*>(a + 4)  = *reinterpret_cast<float4*>(&As[kk][ty * 8 + 4]);
            *reinterpret_cast<float4*>(bb)     = *reinterpret_cast<float4*>(&Bs[kk][tx * 8]);
            *reinterpret_cast<float4*>(bb + 4) = *reinterpret_cast<float4*>(&Bs[kk][tx * 8 + 4]);
            #pragma unroll
            for (int i = 0; i < 8; i++)
                #pragma unroll
                for (int j = 0; j < 8; j++)
                    acc[i][j] += a[i] * bb[j];
        }
        __syncthreads();
    }

    // ---- epilogue: bias + relu ----
    #pragma unroll
    for (int i = 0; i < 8; i++) {
        int row = row0 + ty * 8 + i;
        if (row >= N_NODES) continue;
        #pragma unroll
        for (int j = 0; j < 8; j += 4) {
            int col = tx * 8 + j;
            float4 r;
            r.x = fmaxf(acc[i][j + 0] + bias[col + 0], 0.f);
            r.y = fmaxf(acc[i][j + 1] + bias[col + 1], 0.f);
            r.z = fmaxf(acc[i][j + 2] + bias[col + 2], 0.f);
            r.w = fmaxf(acc[i][j + 3] + bias[col + 3], 0.f);
            *reinterpret_cast<float4*>(out + (size_t)row * D + col) = r;
        }
    }
}

// ---------------- query = metapath_emb @ Wq + bq ---------------------------
__global__ void query_kernel(const float* __restrict__ memb,
                             const float* __restrict__ Wq,
                             const float* __restrict__ bq,
                             float* __restrict__ q) {
    int d = threadIdx.x;   // 0..127
    #pragma unroll
    for (int p = 0; p < NP; p++) {
        float s = bq[d];
        #pragma unroll 8
        for (int k = 0; k < 64; k++)
            s += memb[p * 64 + k] * Wq[k * 128 + d];
        q[p * 128 + d] = s;
    }
}

// ---------------- semantic attention ---------------------------------------
// sems layout [p][n][d]; one warp per node
__global__ void attn_kernel(const float* __restrict__ sems,
                            const float* __restrict__ q,
                            float* __restrict__ out) {
    int warp = (blockIdx.x * blockDim.x + threadIdx.x) >> 5;
    int lane = threadIdx.x & 31;
    if (warp >= NREG) return;

    float e[NP][4];
    float s[NP];
    #pragma unroll
    for (int p = 0; p < NP; p++) {
        float dotv = 0.f;
        #pragma unroll
        for (int c = 0; c < 4; c++) {
            float v = sems[((size_t)p * NREG + warp) * D + c * 32 + lane];
            e[p][c] = v;
            dotv += v * q[p * 128 + c * 32 + lane];
        }
        #pragma unroll
        for (int o = 16; o > 0; o >>= 1)
            dotv += __shfl_xor_sync(0xffffffffu, dotv, o);
        s[p] = dotv * 0.08838834764831843f;   // 1/sqrt(128)
    }
    float mx = fmaxf(fmaxf(s[0], s[1]), fmaxf(s[2], s[3]));
    float w[NP], sum = 0.f;
    #pragma unroll
    for (int p = 0; p < NP; p++) { w[p] = expf(s[p] - mx); sum += w[p]; }
    float inv = 1.0f / sum;
    #pragma unroll
    for (int c = 0; c < 4; c++) {
        float o = 0.f;
        #pragma unroll
        for (int p = 0; p < NP; p++) o += w[p] * inv * e[p][c];
        out[(size_t)warp * D + c * 32 + lane] = o;
    }
}

// ---------------- launch ----------------------------------------------------
extern "C" void kernel_launch(void* const* d_in, const int* in_sizes, int n_in,
                              void* d_out, int out_size) {
    const float* E          = (const float*)d_in[0];
    const float* memb       = (const float*)d_in[1];
    const float* W_root     = (const float*)d_in[2];
    const float* W_rel      = (const float*)d_in[3];
    const float* b          = (const float*)d_in[4];
    const float* Wq         = (const float*)d_in[5];
    const float* bq         = (const float*)d_in[6];
    const int*   edge_index = (const int*)d_in[7];     // int32 (JAX x64 disabled)
    const int*   eids       = (const int*)d_in[8];     // int32
    float* out = (float*)d_out;

    float *x0, *x1, *agg, *cnt, *sems, *query;
    cudaGetSymbolAddress((void**)&x0,    g_x0);
    cudaGetSymbolAddress((void**)&x1,    g_x1);
    cudaGetSymbolAddress((void**)&agg,   g_agg);
    cudaGetSymbolAddress((void**)&cnt,   g_cnt);
    cudaGetSymbolAddress((void**)&sems,  g_sems);
    cudaGetSymbolAddress((void**)&query, g_query);

    const int gatherBlocks  = (N_NODES * (D / 4) + 255) / 256;
    const int scatterBlocks = (N_EDGES * 32 + 255) / 256;
    const int gemmBlocks    = (N_NODES + BM - 1) / BM;

    for (int p = 0; p < NP; p++) {
        gather_kernel<<<gatherBlocks, 256>>>(E, eids + (size_t)p * N_NODES, x0);

        const float* in  = x0;
        float*       outx = x1;
        for (int l = 0; l < NL; l++) {
            cudaMemsetAsync(agg, 0, (size_t)N_NODES * D * sizeof(float));
            cudaMemsetAsync(cnt, 0, (size_t)N_NODES * sizeof(float));
            const int* srcp = edge_index + (size_t)p * 2 * N_EDGES;
            const int* dstp = srcp + N_EDGES;
            scatter_kernel<<<scatterBlocks, 256>>>(in, srcp, dstp, agg, cnt);

            size_t woff = (size_t)(p * NL + l) * D * D;
            rgcn_gemm_kernel<<<gemmBlocks, 256>>>(
                agg, cnt, in,
                W_rel + woff,            // Wm: message weight
                W_root + woff,           // Wr: root weight
                b + (size_t)(p * NL + l) * D,
                outx);

            const float* tmp = in; in = outx; outx = (float*)tmp;
        }
        // after NL=2 layers the result is back in x0 (== in)
        cudaMemcpyAsync(sems + (size_t)p * NREG * D, in,
                        (size_t)NREG * D * sizeof(float),
                        cudaMemcpyDeviceToDevice);
    }

    query_kernel<<<1, 128>>>(memb, Wq, bq, query);
    attn_kernel<<<(NREG + 7) / 8, 256>>>(sems, query, out);
}

// round 6
// speedup vs baseline: 2.0842x; 2.0842x over previous
#include <cuda_runtime.h>
#include <cstdint>
#include <cstddef>

#define N_NODES 100000
#define N_EDGES 1600000
#define NREG    50000
#define D       128
#define NP      4
#define NL      2
#define CAP     128            // max in-degree bucket capacity (Poisson(16): P(>128) ~ 0)

// ---------------- scratch (device globals; no allocations allowed) ----------
__device__ float g_x0[(size_t)N_NODES * D];          // 51.2 MB
__device__ float g_x1[(size_t)N_NODES * D];          // 51.2 MB
__device__ float g_agg[(size_t)N_NODES * D];         // 51.2 MB
__device__ int   g_deg[N_NODES];
__device__ int   g_bucket[(size_t)N_NODES * CAP];    // 51.2 MB dst-bucketed src ids
__device__ float g_sems[(size_t)NP * NREG * D];      // 102.4 MB, layout [p][n][d]
__device__ float g_query[NP * D];

// ---------------- gather: x[n] = E[eids[n]] --------------------------------
__global__ void gather_kernel(const float* __restrict__ E,
                              const int* __restrict__ eids,
                              float* __restrict__ x) {
    int i = blockIdx.x * blockDim.x + threadIdx.x;       // over N_NODES*32 float4
    if (i >= N_NODES * (D / 4)) return;
    int n = i >> 5;
    int c = i & 31;
    int e = eids[n];
    reinterpret_cast<float4*>(x)[(size_t)n * 32 + c] =
        reinterpret_cast<const float4*>(E)[(size_t)e * 32 + c];
}

// ---------------- bucket-CSR build -----------------------------------------
__global__ void csr_fill_kernel(const int* __restrict__ src,
                                const int* __restrict__ dst,
                                int* __restrict__ deg,
                                int* __restrict__ bucket) {
    int i = blockIdx.x * blockDim.x + threadIdx.x;
    if (i >= N_EDGES) return;
    int d = dst[i];
    int p = atomicAdd(deg + d, 1);
    if (p < CAP) bucket[(size_t)d * CAP + p] = src[i];
}

// ---------------- pull aggregation: agg[n] = mean_{e: dst=n} x[src[e]] -----
// one warp per node; lane owns one float4 of the 128-d row
__global__ void agg_kernel(const float* __restrict__ x,
                           const int* __restrict__ deg,
                           const int* __restrict__ bucket,
                           float* __restrict__ agg,
                           int nNodes) {
    int warp = (blockIdx.x * blockDim.x + threadIdx.x) >> 5;
    int lane = threadIdx.x & 31;
    if (warp >= nNodes) return;
    int dg = deg[warp];
    int n  = dg < CAP ? dg : CAP;
    const int* b = bucket + (size_t)warp * CAP;
    const float4* x4 = reinterpret_cast<const float4*>(x);

    float4 acc = make_float4(0.f, 0.f, 0.f, 0.f);
    int e = 0;
    for (; e + 4 <= n; e += 4) {
        int s0 = b[e], s1 = b[e + 1], s2 = b[e + 2], s3 = b[e + 3];
        float4 v0 = x4[(size_t)s0 * 32 + lane];
        float4 v1 = x4[(size_t)s1 * 32 + lane];
        float4 v2 = x4[(size_t)s2 * 32 + lane];
        float4 v3 = x4[(size_t)s3 * 32 + lane];
        acc.x += (v0.x + v1.x) + (v2.x + v3.x);
        acc.y += (v0.y + v1.y) + (v2.y + v3.y);
        acc.z += (v0.z + v1.z) + (v2.z + v3.z);
        acc.w += (v0.w + v1.w) + (v2.w + v3.w);
    }
    for (; e < n; e++) {
        float4 v = x4[(size_t)b[e] * 32 + lane];
        acc.x += v.x; acc.y += v.y; acc.z += v.z; acc.w += v.w;
    }
    float rinv = 1.0f / fmaxf((float)dg, 1.0f);
    acc.x *= rinv; acc.y *= rinv; acc.z *= rinv; acc.w *= rinv;
    reinterpret_cast<float4*>(agg)[(size_t)warp * 32 + lane] = acc;
}

// ---------------- fused RGCN GEMM ------------------------------------------
// out = relu( agg @ Wm + x @ Wr + bias ), treated as [agg | x] (K=256) @ [Wm ; Wr]
#define BM 128
#define BN 128
#define BK 16

__global__ __launch_bounds__(256)
void rgcn_gemm_kernel(const float* __restrict__ agg,   // already mean-normalized
                      const float* __restrict__ x,
                      const float* __restrict__ Wm,    // message weight (W_rel)
                      const float* __restrict__ Wr,    // root weight (W_root)
                      const float* __restrict__ bias,
                      float* __restrict__ out,
                      int M) {
    __shared__ float As[BK][BM + 4];
    __shared__ float Bs[BK][BN];

    int row0 = blockIdx.x * BM;
    int t  = threadIdx.x;
    int ty = t >> 4;          // 0..15
    int tx = t & 15;          // 0..15

    float acc[8][8];
    #pragma unroll
    for (int i = 0; i < 8; i++)
        #pragma unroll
        for (int j = 0; j < 8; j++) acc[i][j] = 0.0f;

    int la_row = t >> 2;          // 0..63
    int la_k4  = (t & 3) * 4;     // 0,4,8,12

    #pragma unroll 1
    for (int kt = 0; kt < 256 / BK; kt++) {
        int k0 = kt * BK;
        // ---- load A tile (128 rows x 16 k) ----
        #pragma unroll
        for (int h = 0; h < 2; h++) {
            int row = row0 + la_row + h * 64;
            float4 v = make_float4(0.f, 0.f, 0.f, 0.f);
            if (row < M) {
                int kk = k0 + la_k4;
                const float* A = (kk < 128)
                    ? (agg + (size_t)row * D + kk)
                    : (x   + (size_t)row * D + (kk - 128));
                v = *reinterpret_cast<const float4*>(A);
            }
            As[la_k4 + 0][la_row + h * 64] = v.x;
            As[la_k4 + 1][la_row + h * 64] = v.y;
            As[la_k4 + 2][la_row + h * 64] = v.z;
            As[la_k4 + 3][la_row + h * 64] = v.w;
        }
        // ---- load B tile (16 k x 128 n) ----
        #pragma unroll
        for (int h = 0; h < 2; h++) {
            int s  = t + h * 256;          // 0..511 float4 slots
            int kB = s >> 5;               // 0..15
            int n4 = (s & 31) * 4;         // 0..124
            int kk = k0 + kB;
            const float* W = (kk < 128)
                ? (Wm + (size_t)kk * 128 + n4)
                : (Wr + (size_t)(kk - 128) * 128 + n4);
            *reinterpret_cast<float4*>(&Bs[kB][n4]) =
                *reinterpret_cast<const float4*>(W);
        }
        __syncthreads();

        #pragma unroll
        for (int kk = 0; kk < BK; kk++) {
            float a[8], bb[8];
            *reinterpret_cast<float4*>(a)      = *reinterpret_cast<float4*>(&As[kk][ty * 8]);
            *reinterpret_cast<float4*>(a + 4)  = *reinterpret_cast<float4*>(&As[kk][ty * 8 + 4]);
            *reinterpret_cast<float4*>(bb)     = *reinterpret_cast<float4*>(&Bs[kk][tx * 8]);
            *reinterpret_cast<float4*>(bb + 4) = *reinterpret_cast<float4*>(&Bs[kk][tx * 8 + 4]);
            #pragma unroll
            for (int i = 0; i < 8; i++)
                #pragma unroll
                for (int j = 0; j < 8; j++)
                    acc[i][j] += a[i] * bb[j];
        }
        __syncthreads();
    }

    // ---- epilogue: bias + relu ----
    #pragma unroll
    for (int i = 0; i < 8; i++) {
        int row = row0 + ty * 8 + i;
        if (row >= M) continue;
        #pragma unroll
        for (int j = 0; j < 8; j += 4) {
            int col = tx * 8 + j;
            float4 r;
            r.x = fmaxf(acc[i][j + 0] + bias[col + 0], 0.f);
            r.y = fmaxf(acc[i][j + 1] + bias[col + 1], 0.f);
            r.z = fmaxf(acc[i][j + 2] + bias[col + 2], 0.f);
            r.w = fmaxf(acc[i][j + 3] + bias[col + 3], 0.f);
            *reinterpret_cast<float4*>(out + (size_t)row * D + col) = r;
        }
    }
}

// ---------------- query = metapath_emb @ Wq + bq ---------------------------
__global__ void query_kernel(const float* __restrict__ memb,
                             const float* __restrict__ Wq,
                             const float* __restrict__ bq,
                             float* __restrict__ q) {
    int d = threadIdx.x;   // 0..127
    #pragma unroll
    for (int p = 0; p < NP; p++) {
        float s = bq[d];
        #pragma unroll 8
        for (int k = 0; k < 64; k++)
            s += memb[p * 64 + k] * Wq[k * 128 + d];
        q[p * 128 + d] = s;
    }
}

// ---------------- semantic attention ---------------------------------------
// sems layout [p][n][d]; one warp per node
__global__ void attn_kernel(const float* __restrict__ sems,
                            const float* __restrict__ q,
                            float* __restrict__ out) {
    int warp = (blockIdx.x * blockDim.x + threadIdx.x) >> 5;
    int lane = threadIdx.x & 31;
    if (warp >= NREG) return;

    float e[NP][4];
    float s[NP];
    #pragma unroll
    for (int p = 0; p < NP; p++) {
        float dotv = 0.f;
        #pragma unroll
        for (int c = 0; c < 4; c++) {
            float v = sems[((size_t)p * NREG + warp) * D + c * 32 + lane];
            e[p][c] = v;
            dotv += v * q[p * 128 + c * 32 + lane];
        }
        #pragma unroll
        for (int o = 16; o > 0; o >>= 1)
            dotv += __shfl_xor_sync(0xffffffffu, dotv, o);
        s[p] = dotv * 0.08838834764831843f;   // 1/sqrt(128)
    }
    float mx = fmaxf(fmaxf(s[0], s[1]), fmaxf(s[2], s[3]));
    float w[NP], sum = 0.f;
    #pragma unroll
    for (int p = 0; p < NP; p++) { w[p] = expf(s[p] - mx); sum += w[p]; }
    float inv = 1.0f / sum;
    #pragma unroll
    for (int c = 0; c < 4; c++) {
        float o = 0.f;
        #pragma unroll
        for (int p = 0; p < NP; p++) o += w[p] * inv * e[p][c];
        out[(size_t)warp * D + c * 32 + lane] = o;
    }
}

// ---------------- launch ----------------------------------------------------
extern "C" void kernel_launch(void* const* d_in, const int* in_sizes, int n_in,
                              void* d_out, int out_size) {
    const float* E          = (const float*)d_in[0];
    const float* memb       = (const float*)d_in[1];
    const float* W_root     = (const float*)d_in[2];
    const float* W_rel      = (const float*)d_in[3];
    const float* b          = (const float*)d_in[4];
    const float* Wq         = (const float*)d_in[5];
    const float* bq         = (const float*)d_in[6];
    const int*   edge_index = (const int*)d_in[7];     // int32
    const int*   eids       = (const int*)d_in[8];     // int32
    float* out = (float*)d_out;

    float *x0, *x1, *agg, *sems, *query;
    int *deg, *bucket;
    cudaGetSymbolAddress((void**)&x0,     g_x0);
    cudaGetSymbolAddress((void**)&x1,     g_x1);
    cudaGetSymbolAddress((void**)&agg,    g_agg);
    cudaGetSymbolAddress((void**)&deg,    g_deg);
    cudaGetSymbolAddress((void**)&bucket, g_bucket);
    cudaGetSymbolAddress((void**)&sems,   g_sems);
    cudaGetSymbolAddress((void**)&query,  g_query);

    const int gatherBlocks = (N_NODES * (D / 4) + 255) / 256;
    const int fillBlocks   = (N_EDGES + 255) / 256;
    const int aggBlocksF   = (N_NODES * 32 + 255) / 256;   // full: warp per node
    const int aggBlocksH   = (NREG * 32 + 255) / 256;      // half
    const int gemmBlocksF  = (N_NODES + BM - 1) / BM;
    const int gemmBlocksH  = (NREG + BM - 1) / BM;

    for (int p = 0; p < NP; p++) {
        gather_kernel<<<gatherBlocks, 256>>>(E, eids + (size_t)p * N_NODES, x0);

        // build dst-bucketed edge table once per meta-path (shared by both layers)
        cudaMemsetAsync(deg, 0, N_NODES * sizeof(int));
        const int* srcp = edge_index + (size_t)p * 2 * N_EDGES;
        const int* dstp = srcp + N_EDGES;
        csr_fill_kernel<<<fillBlocks, 256>>>(srcp, dstp, deg, bucket);

        size_t w0 = (size_t)(p * NL + 0) * D * D;
        size_t w1 = (size_t)(p * NL + 1) * D * D;

        // layer 0: full width
        agg_kernel<<<aggBlocksF, 256>>>(x0, deg, bucket, agg, N_NODES);
        rgcn_gemm_kernel<<<gemmBlocksF, 256>>>(
            agg, x0, W_rel + w0, W_root + w0,
            b + (size_t)(p * NL + 0) * D, x1, N_NODES);

        // layer 1: only rows < NREG are consumed -> write straight into sems
        agg_kernel<<<aggBlocksH, 256>>>(x1, deg, bucket, agg, NREG);
        rgcn_gemm_kernel<<<gemmBlocksH, 256>>>(
            agg, x1, W_rel + w1, W_root + w1,
            b + (size_t)(p * NL + 1) * D,
            sems + (size_t)p * NREG * D, NREG);
    }

    query_kernel<<<1, 128>>>(memb, Wq, bq, query);
    attn_kernel<<<(NREG + 7) / 8, 256>>>(sems, query, out);
}

// round 12
// speedup vs baseline: 2.3300x; 1.1179x over previous
#include <cuda_runtime.h>
#include <cuda_bf16.h>
#include <cstdint>
#include <cstddef>

#define N_NODES 100000
#define N_EDGES 1600000
#define NREG    50000
#define D       128
#define NP      4
#define NL      2
#define CAP     128

// ---------------- scratch (device globals) ----------------------------------
__device__ float g_x0[(size_t)N_NODES * D];
__device__ float g_x1[(size_t)N_NODES * D];
__device__ float g_agg[(size_t)N_NODES * D];
__device__ int   g_deg[N_NODES];
__device__ int   g_bucket[(size_t)N_NODES * CAP];
__device__ float g_sems[(size_t)NP * NREG * D];
__device__ float g_query[NP * D];
// precomputed B fragments: [kt(16)][nt(16)][lane(32)] -> uint4{b0_hi,b1_hi,b0_lo,b1_lo}
__device__ __align__(16) uint4 g_bfrag[16 * 16 * 32];

// ---------------- helpers ----------------------------------------------------
__device__ __forceinline__ uint32_t pack_bf16x2(float lo, float hi) {
    __nv_bfloat162 h;
    h.x = __float2bfloat16(lo);   // low 16 bits = first element
    h.y = __float2bfloat16(hi);
    return *reinterpret_cast<uint32_t*>(&h);
}
__device__ __forceinline__ void split2(float a, float b, uint32_t& hi, uint32_t& lo) {
    __nv_bfloat16 ha = __float2bfloat16(a);
    __nv_bfloat16 hb = __float2bfloat16(b);
    hi = pack_bf16x2(__bfloat162float(ha), __bfloat162float(hb));
    // recompute exact hi floats for residual
    float fa = __bfloat162float(ha), fb = __bfloat162float(hb);
    lo = pack_bf16x2(a - fa, b - fb);
}
__device__ __forceinline__ void mma_bf16(float* d, const uint32_t* a, uint32_t b0, uint32_t b1) {
    asm volatile(
        "mma.sync.aligned.m16n8k16.row.col.f32.bf16.bf16.f32 "
        "{%0,%1,%2,%3}, {%4,%5,%6,%7}, {%8,%9}, {%0,%1,%2,%3};"
        : "+f"(d[0]), "+f"(d[1]), "+f"(d[2]), "+f"(d[3])
        : "r"(a[0]), "r"(a[1]), "r"(a[2]), "r"(a[3]), "r"(b0), "r"(b1));
}

// ---------------- gather ----------------------------------------------------
__global__ void gather_kernel(const float* __restrict__ E,
                              const int* __restrict__ eids,
                              float* __restrict__ x) {
    int i = blockIdx.x * blockDim.x + threadIdx.x;
    if (i >= N_NODES * (D / 4)) return;
    int n = i >> 5, c = i & 31;
    int e = eids[n];
    reinterpret_cast<float4*>(x)[(size_t)n * 32 + c] =
        reinterpret_cast<const float4*>(E)[(size_t)e * 32 + c];
}

// ---------------- bucket-CSR build ------------------------------------------
__global__ void csr_fill_kernel(const int* __restrict__ src,
                                const int* __restrict__ dst,
                                int* __restrict__ deg,
                                int* __restrict__ bucket) {
    int i = blockIdx.x * blockDim.x + threadIdx.x;
    if (i >= N_EDGES) return;
    int d = dst[i];
    int p = atomicAdd(deg + d, 1);
    if (p < CAP) bucket[(size_t)d * CAP + p] = src[i];
}

// ---------------- pull aggregation ------------------------------------------
__global__ void agg_kernel(const float* __restrict__ x,
                           const int* __restrict__ deg,
                           const int* __restrict__ bucket,
                           float* __restrict__ agg,
                           int nNodes) {
    int warp = (blockIdx.x * blockDim.x + threadIdx.x) >> 5;
    int lane = threadIdx.x & 31;
    if (warp >= nNodes) return;
    int dg = deg[warp];
    int n  = dg < CAP ? dg : CAP;
    const int* b = bucket + (size_t)warp * CAP;
    const float4* x4 = reinterpret_cast<const float4*>(x);

    float4 acc = make_float4(0.f, 0.f, 0.f, 0.f);
    int e = 0;
    for (; e + 4 <= n; e += 4) {
        int s0 = b[e], s1 = b[e+1], s2 = b[e+2], s3 = b[e+3];
        float4 v0 = x4[(size_t)s0 * 32 + lane];
        float4 v1 = x4[(size_t)s1 * 32 + lane];
        float4 v2 = x4[(size_t)s2 * 32 + lane];
        float4 v3 = x4[(size_t)s3 * 32 + lane];
        acc.x += (v0.x + v1.x) + (v2.x + v3.x);
        acc.y += (v0.y + v1.y) + (v2.y + v3.y);
        acc.z += (v0.z + v1.z) + (v2.z + v3.z);
        acc.w += (v0.w + v1.w) + (v2.w + v3.w);
    }
    for (; e < n; e++) {
        float4 v = x4[(size_t)b[e] * 32 + lane];
        acc.x += v.x; acc.y += v.y; acc.z += v.z; acc.w += v.w;
    }
    float rinv = 1.0f / fmaxf((float)dg, 1.0f);
    acc.x *= rinv; acc.y *= rinv; acc.z *= rinv; acc.w *= rinv;
    reinterpret_cast<float4*>(agg)[(size_t)warp * 32 + lane] = acc;
}

// ---------------- weight prep: build per-lane B fragments --------------------
// B operand is col-major k(256) x n(128): element (k,n) = Wm[k][n] (k<128) / Wr[k-128][n]
// m16n8k16 B frag: lane t holds b0 = (k=(t%4)*2, +1 ; n=t/4), b1 = (k+8, +9 ; n=t/4)
__global__ void wprep_kernel(const float* __restrict__ Wm,
                             const float* __restrict__ Wr,
                             uint4* __restrict__ bfrag) {
    int i = blockIdx.x * blockDim.x + threadIdx.x;   // 0..8191
    if (i >= 16 * 16 * 32) return;
    int lane = i & 31;
    int nt   = (i >> 5) & 15;
    int kt   = i >> 9;
    int n  = nt * 8 + (lane >> 2);
    int k0 = kt * 16 + (lane & 3) * 2;

    float w[4];
    #pragma unroll
    for (int j = 0; j < 4; j++) {
        int k = k0 + (j >> 1) * 8 + (j & 1);          // k0, k0+1, k0+8, k0+9
        w[j] = (k < 128) ? Wm[k * 128 + n] : Wr[(k - 128) * 128 + n];
    }
    uint4 r;
    split2(w[0], w[1], r.x, r.z);    // b0: hi in .x, lo in .z
    split2(w[2], w[3], r.y, r.w);    // b1: hi in .y, lo in .w
    bfrag[i] = r;
}

// ---------------- mma.sync RGCN GEMM -----------------------------------------
// out = relu([agg | x](M x 256) @ W + bias); bf16 split: Ah*Bh + Ah*Bl + Al*Bh
__global__ void __launch_bounds__(256)
rgcn_gemm_mma(const float* __restrict__ agg,
              const float* __restrict__ x,
              const uint4* __restrict__ bfrag,
              const float* __restrict__ bias,
              float* __restrict__ out, int M) {
    int tid = threadIdx.x;
    int w   = tid >> 5;
    int lane = tid & 31;
    int row0  = blockIdx.x * 128 + (w & 1) * 64;     // warp's 64-row slice
    int nwarp = (w >> 1);                            // 0..3 -> 32-col slice
    int ncol0 = nwarp * 32;
    int tr = lane >> 2;        // 0..7
    int tc = lane & 3;         // 0..3

    float acc[4][4][4];
    #pragma unroll
    for (int mt = 0; mt < 4; mt++)
        #pragma unroll
        for (int nt = 0; nt < 4; nt++)
            #pragma unroll
            for (int j = 0; j < 4; j++) acc[mt][nt][j] = 0.f;

    #pragma unroll 1
    for (int kt = 0; kt < 16; kt++) {
        int kg = kt * 16 + tc * 2;                   // global k of first element
        const float* Ab;
        int koff;
        if (kg < 128) { Ab = agg; koff = kg; }
        else          { Ab = x;   koff = kg - 128; }

        // load + split A fragments for 4 m-tiles
        uint32_t ahi[4][4], alo[4][4];
        #pragma unroll
        for (int mt = 0; mt < 4; mt++) {
            int r = row0 + mt * 16 + tr;
            bool ok0 = (r < M), ok1 = (r + 8 < M);
            float2 p00 = ok0 ? *reinterpret_cast<const float2*>(Ab + (size_t)r * D + koff)
                             : make_float2(0.f, 0.f);
            float2 p01 = ok0 ? *reinterpret_cast<const float2*>(Ab + (size_t)r * D + koff + 8)
                             : make_float2(0.f, 0.f);
            float2 p10 = ok1 ? *reinterpret_cast<const float2*>(Ab + (size_t)(r + 8) * D + koff)
                             : make_float2(0.f, 0.f);
            float2 p11 = ok1 ? *reinterpret_cast<const float2*>(Ab + (size_t)(r + 8) * D + koff + 8)
                             : make_float2(0.f, 0.f);
            split2(p00.x, p00.y, ahi[mt][0], alo[mt][0]);   // a0: (r,   k0..k0+1)
            split2(p10.x, p10.y, ahi[mt][1], alo[mt][1]);   // a1: (r+8, k0..k0+1)
            split2(p01.x, p01.y, ahi[mt][2], alo[mt][2]);   // a2: (r,   k0+8..+9)
            split2(p11.x, p11.y, ahi[mt][3], alo[mt][3]);   // a3: (r+8, k0+8..+9)
        }

        #pragma unroll
        for (int nt = 0; nt < 4; nt++) {
            uint4 bf = __ldg(&bfrag[((size_t)kt * 16 + nwarp * 4 + nt) * 32 + lane]);
            #pragma unroll
            for (int mt = 0; mt < 4; mt++) {
                mma_bf16(acc[mt][nt], ahi[mt], bf.x, bf.y);   // Ah*Bh
                mma_bf16(acc[mt][nt], ahi[mt], bf.z, bf.w);   // Ah*Bl
                mma_bf16(acc[mt][nt], alo[mt], bf.x, bf.y);   // Al*Bh
            }
        }
    }

    // ---- epilogue: bias + relu ----
    float2 b2[4];
    #pragma unroll
    for (int nt = 0; nt < 4; nt++)
        b2[nt] = *reinterpret_cast<const float2*>(bias + ncol0 + nt * 8 + tc * 2);

    #pragma unroll
    for (int mt = 0; mt < 4; mt++) {
        int r0 = row0 + mt * 16 + tr;
        int r1 = r0 + 8;
        #pragma unroll
        for (int nt = 0; nt < 4; nt++) {
            int n = ncol0 + nt * 8 + tc * 2;
            if (r0 < M) {
                float2 v;
                v.x = fmaxf(acc[mt][nt][0] + b2[nt].x, 0.f);
                v.y = fmaxf(acc[mt][nt][1] + b2[nt].y, 0.f);
                *reinterpret_cast<float2*>(out + (size_t)r0 * D + n) = v;
            }
            if (r1 < M) {
                float2 v;
                v.x = fmaxf(acc[mt][nt][2] + b2[nt].x, 0.f);
                v.y = fmaxf(acc[mt][nt][3] + b2[nt].y, 0.f);
                *reinterpret_cast<float2*>(out + (size_t)r1 * D + n) = v;
            }
        }
    }
}

// ---------------- query -----------------------------------------------------
__global__ void query_kernel(const float* __restrict__ memb,
                             const float* __restrict__ Wq,
                             const float* __restrict__ bq,
                             float* __restrict__ q) {
    int d = threadIdx.x;
    #pragma unroll
    for (int p = 0; p < NP; p++) {
        float s = bq[d];
        #pragma unroll 8
        for (int k = 0; k < 64; k++)
            s += memb[p * 64 + k] * Wq[k * 128 + d];
        q[p * 128 + d] = s;
    }
}

// ---------------- semantic attention ----------------------------------------
__global__ void attn_kernel(const float* __restrict__ sems,
                            const float* __restrict__ q,
                            float* __restrict__ out) {
    int warp = (blockIdx.x * blockDim.x + threadIdx.x) >> 5;
    int lane = threadIdx.x & 31;
    if (warp >= NREG) return;

    float e[NP][4];
    float s[NP];
    #pragma unroll
    for (int p = 0; p < NP; p++) {
        float dotv = 0.f;
        #pragma unroll
        for (int c = 0; c < 4; c++) {
            float v = sems[((size_t)p * NREG + warp) * D + c * 32 + lane];
            e[p][c] = v;
            dotv += v * q[p * 128 + c * 32 + lane];
        }
        #pragma unroll
        for (int o = 16; o > 0; o >>= 1)
            dotv += __shfl_xor_sync(0xffffffffu, dotv, o);
        s[p] = dotv * 0.08838834764831843f;
    }
    float mx = fmaxf(fmaxf(s[0], s[1]), fmaxf(s[2], s[3]));
    float w[NP], sum = 0.f;
    #pragma unroll
    for (int p = 0; p < NP; p++) { w[p] = expf(s[p] - mx); sum += w[p]; }
    float inv = 1.0f / sum;
    #pragma unroll
    for (int c = 0; c < 4; c++) {
        float o = 0.f;
        #pragma unroll
        for (int p = 0; p < NP; p++) o += w[p] * inv * e[p][c];
        out[(size_t)warp * D + c * 32 + lane] = o;
    }
}

// ---------------- launch ----------------------------------------------------
extern "C" void kernel_launch(void* const* d_in, const int* in_sizes, int n_in,
                              void* d_out, int out_size) {
    const float* E          = (const float*)d_in[0];
    const float* memb       = (const float*)d_in[1];
    const float* W_root     = (const float*)d_in[2];
    const float* W_rel      = (const float*)d_in[3];
    const float* b          = (const float*)d_in[4];
    const float* Wq         = (const float*)d_in[5];
    const float* bq         = (const float*)d_in[6];
    const int*   edge_index = (const int*)d_in[7];
    const int*   eids       = (const int*)d_in[8];
    float* out = (float*)d_out;

    float *x0, *x1, *agg, *sems, *query;
    int *deg, *bucket;
    uint4* bfrag;
    cudaGetSymbolAddress((void**)&x0,     g_x0);
    cudaGetSymbolAddress((void**)&x1,     g_x1);
    cudaGetSymbolAddress((void**)&agg,    g_agg);
    cudaGetSymbolAddress((void**)&deg,    g_deg);
    cudaGetSymbolAddress((void**)&bucket, g_bucket);
    cudaGetSymbolAddress((void**)&sems,   g_sems);
    cudaGetSymbolAddress((void**)&query,  g_query);
    cudaGetSymbolAddress((void**)&bfrag,  g_bfrag);

    const int gatherBlocks = (N_NODES * (D / 4) + 255) / 256;
    const int fillBlocks   = (N_EDGES + 255) / 256;
    const int aggBlocksF   = (N_NODES * 32 + 255) / 256;
    const int aggBlocksH   = (NREG * 32 + 255) / 256;
    const int gemmBlocksF  = (N_NODES + 127) / 128;
    const int gemmBlocksH  = (NREG + 127) / 128;

    for (int p = 0; p < NP; p++) {
        gather_kernel<<<gatherBlocks, 256>>>(E, eids + (size_t)p * N_NODES, x0);

        cudaMemsetAsync(deg, 0, N_NODES * sizeof(int));
        const int* srcp = edge_index + (size_t)p * 2 * N_EDGES;
        const int* dstp = srcp + N_EDGES;
        csr_fill_kernel<<<fillBlocks, 256>>>(srcp, dstp, deg, bucket);

        size_t w0 = (size_t)(p * NL + 0) * D * D;
        size_t w1 = (size_t)(p * NL + 1) * D * D;

        // layer 0 (full width)
        wprep_kernel<<<32, 256>>>(W_rel + w0, W_root + w0, bfrag);
        agg_kernel<<<aggBlocksF, 256>>>(x0, deg, bucket, agg, N_NODES);
        rgcn_gemm_mma<<<gemmBlocksF, 256>>>(
            agg, x0, bfrag, b + (size_t)(p * NL + 0) * D, x1, N_NODES);

        // layer 1 (only rows < NREG consumed) -> write straight into sems
        wprep_kernel<<<32, 256>>>(W_rel + w1, W_root + w1, bfrag);
        agg_kernel<<<aggBlocksH, 256>>>(x1, deg, bucket, agg, NREG);
        rgcn_gemm_mma<<<gemmBlocksH, 256>>>(
            agg, x1, bfrag, b + (size_t)(p * NL + 1) * D,
            sems + (size_t)p * NREG * D, NREG);
    }

    query_kernel<<<1, 128>>>(memb, Wq, bq, query);
    attn_kernel<<<(NREG + 7) / 8, 256>>>(sems, query, out);
}

// round 13
// speedup vs baseline: 3.4506x; 1.4810x over previous
#include <cuda_runtime.h>
#include <cuda_bf16.h>
#include <cstdint>
#include <cstddef>

#define N_NODES 100000
#define N_EDGES 1600000
#define NREG    50000
#define D       128
#define NP      4
#define NL      2
#define CAP     128

// ---------------- scratch (device globals) ----------------------------------
__device__ float g_x0[(size_t)N_NODES * D];
__device__ float g_x1[(size_t)N_NODES * D];
__device__ float g_sems[(size_t)NP * NREG * D];
__device__ float g_query[NP * D];
__device__ int   g_deg[N_NODES];
__device__ int   g_bucket[(size_t)N_NODES * CAP];
// bf16 split planes (hi/lo) for GEMM A operands
__device__ __nv_bfloat16 g_x0h[(size_t)N_NODES * D];
__device__ __nv_bfloat16 g_x0l[(size_t)N_NODES * D];
__device__ __nv_bfloat16 g_x1h[(size_t)N_NODES * D];
__device__ __nv_bfloat16 g_x1l[(size_t)N_NODES * D];
__device__ __nv_bfloat16 g_aggh[(size_t)N_NODES * D];
__device__ __nv_bfloat16 g_aggl[(size_t)N_NODES * D];
// precomputed B fragments: [kt(16)][nt(16)][lane(32)] -> uint4{b0_hi,b1_hi,b0_lo,b1_lo}
__device__ __align__(16) uint4 g_bfrag[16 * 16 * 32];

// ---------------- helpers ----------------------------------------------------
__device__ __forceinline__ uint32_t smem_u32(const void* p) {
    uint32_t a;
    asm("{ .reg .u64 t; cvta.to.shared.u64 t, %1; cvt.u32.u64 %0, t; }" : "=r"(a) : "l"(p));
    return a;
}
__device__ __forceinline__ uint32_t pack_bf16x2(float lo, float hi) {
    __nv_bfloat162 h;
    h.x = __float2bfloat16(lo);
    h.y = __float2bfloat16(hi);
    return *reinterpret_cast<uint32_t*>(&h);
}
__device__ __forceinline__ void split2(float a, float b, uint32_t& hi, uint32_t& lo) {
    __nv_bfloat16 ha = __float2bfloat16(a);
    __nv_bfloat16 hb = __float2bfloat16(b);
    float fa = __bfloat162float(ha), fb = __bfloat162float(hb);
    hi = pack_bf16x2(fa, fb);
    lo = pack_bf16x2(a - fa, b - fb);
}
__device__ __forceinline__ void mma_bf16(float* d, const uint32_t* a, uint32_t b0, uint32_t b1) {
    asm volatile(
        "mma.sync.aligned.m16n8k16.row.col.f32.bf16.bf16.f32 "
        "{%0,%1,%2,%3}, {%4,%5,%6,%7}, {%8,%9}, {%0,%1,%2,%3};"
        : "+f"(d[0]), "+f"(d[1]), "+f"(d[2]), "+f"(d[3])
        : "r"(a[0]), "r"(a[1]), "r"(a[2]), "r"(a[3]), "r"(b0), "r"(b1));
}
__device__ __forceinline__ void ldmat_x4(uint32_t* r, uint32_t addr) {
    asm volatile("ldmatrix.sync.aligned.m8n8.x4.shared.b16 {%0,%1,%2,%3}, [%4];"
                 : "=r"(r[0]), "=r"(r[1]), "=r"(r[2]), "=r"(r[3]) : "r"(addr));
}
__device__ __forceinline__ void cp16(uint32_t dst, const void* src, bool pred) {
    int sz = pred ? 16 : 0;
    asm volatile("cp.async.cg.shared.global [%0], [%1], 16, %2;"
                 :: "r"(dst), "l"(src), "r"(sz));
}
#define CP_COMMIT() asm volatile("cp.async.commit_group;" ::: "memory")
#define CP_WAIT(n)  asm volatile("cp.async.wait_group %0;" :: "n"(n) : "memory")

// ---------------- gather: x[n]=E[eids[n]] (+ bf16 split planes) --------------
__global__ void gather_kernel(const float* __restrict__ E,
                              const int* __restrict__ eids,
                              float* __restrict__ x,
                              __nv_bfloat16* __restrict__ xh,
                              __nv_bfloat16* __restrict__ xl) {
    int i = blockIdx.x * blockDim.x + threadIdx.x;
    if (i >= N_NODES * (D / 4)) return;
    int n = i >> 5, c = i & 31;
    int e = eids[n];
    float4 v = reinterpret_cast<const float4*>(E)[(size_t)e * 32 + c];
    reinterpret_cast<float4*>(x)[(size_t)n * 32 + c] = v;
    uint2 h2, l2;
    split2(v.x, v.y, h2.x, l2.x);
    split2(v.z, v.w, h2.y, l2.y);
    reinterpret_cast<uint2*>(xh)[(size_t)n * 32 + c] = h2;
    reinterpret_cast<uint2*>(xl)[(size_t)n * 32 + c] = l2;
}

// ---------------- bucket-CSR build ------------------------------------------
__global__ void csr_fill_kernel(const int* __restrict__ src,
                                const int* __restrict__ dst,
                                int* __restrict__ deg,
                                int* __restrict__ bucket) {
    int i = blockIdx.x * blockDim.x + threadIdx.x;
    if (i >= N_EDGES) return;
    int d = dst[i];
    int p = atomicAdd(deg + d, 1);
    if (p < CAP) bucket[(size_t)d * CAP + p] = src[i];
}

// ---------------- pull aggregation -> bf16 split planes ----------------------
__global__ void agg_kernel(const float* __restrict__ x,
                           const int* __restrict__ deg,
                           const int* __restrict__ bucket,
                           __nv_bfloat16* __restrict__ aggh,
                           __nv_bfloat16* __restrict__ aggl,
                           int nNodes) {
    int warp = (blockIdx.x * blockDim.x + threadIdx.x) >> 5;
    int lane = threadIdx.x & 31;
    if (warp >= nNodes) return;
    int dg = deg[warp];
    int n  = dg < CAP ? dg : CAP;
    const int* b = bucket + (size_t)warp * CAP;
    const float4* x4 = reinterpret_cast<const float4*>(x);

    float4 acc = make_float4(0.f, 0.f, 0.f, 0.f);
    int e = 0;
    for (; e + 4 <= n; e += 4) {
        int s0 = b[e], s1 = b[e+1], s2 = b[e+2], s3 = b[e+3];
        float4 v0 = x4[(size_t)s0 * 32 + lane];
        float4 v1 = x4[(size_t)s1 * 32 + lane];
        float4 v2 = x4[(size_t)s2 * 32 + lane];
        float4 v3 = x4[(size_t)s3 * 32 + lane];
        acc.x += (v0.x + v1.x) + (v2.x + v3.x);
        acc.y += (v0.y + v1.y) + (v2.y + v3.y);
        acc.z += (v0.z + v1.z) + (v2.z + v3.z);
        acc.w += (v0.w + v1.w) + (v2.w + v3.w);
    }
    for (; e < n; e++) {
        float4 v = x4[(size_t)b[e] * 32 + lane];
        acc.x += v.x; acc.y += v.y; acc.z += v.z; acc.w += v.w;
    }
    float rinv = 1.0f / fmaxf((float)dg, 1.0f);
    acc.x *= rinv; acc.y *= rinv; acc.z *= rinv; acc.w *= rinv;
    uint2 h2, l2;
    split2(acc.x, acc.y, h2.x, l2.x);
    split2(acc.z, acc.w, h2.y, l2.y);
    reinterpret_cast<uint2*>(aggh)[(size_t)warp * 32 + lane] = h2;
    reinterpret_cast<uint2*>(aggl)[(size_t)warp * 32 + lane] = l2;
}

// ---------------- weight prep: per-lane B fragments --------------------------
__global__ void wprep_kernel(const float* __restrict__ Wm,
                             const float* __restrict__ Wr,
                             uint4* __restrict__ bfrag) {
    int i = blockIdx.x * blockDim.x + threadIdx.x;
    if (i >= 16 * 16 * 32) return;
    int lane = i & 31;
    int nt   = (i >> 5) & 15;
    int kt   = i >> 9;
    int n  = nt * 8 + (lane >> 2);
    int k0 = kt * 16 + (lane & 3) * 2;

    float w[4];
    #pragma unroll
    for (int j = 0; j < 4; j++) {
        int k = k0 + (j >> 1) * 8 + (j & 1);
        w[j] = (k < 128) ? Wm[k * 128 + n] : Wr[(k - 128) * 128 + n];
    }
    uint4 r;
    split2(w[0], w[1], r.x, r.z);
    split2(w[2], w[3], r.y, r.w);
    bfrag[i] = r;
}

// ---------------- mma.sync RGCN GEMM (smem-staged, cp.async + ldmatrix) ------
// A = [agg | x] (M x 256) pre-split bf16; out = relu(A@W + bias) (+ split out)
#define GEMM_SMEM 65536

__device__ __forceinline__ void gemm_prefetch(
    uint32_t sbase, int buf,
    const __nv_bfloat16* __restrict__ hsrc,
    const __nv_bfloat16* __restrict__ lsrc,
    int col, int row0, int M, int t) {
    int grp = t & 7;
    #pragma unroll
    for (int i = 0; i < 4; i++) {
        int row  = (t >> 3) + i * 32;          // 0..127
        int grow = row0 + row;
        uint32_t dst = sbase + (uint32_t)buf * 32768u + (uint32_t)row * 128u
                     + (uint32_t)((grp ^ (row & 7)) << 4);
        const __nv_bfloat16* sh = hsrc + (size_t)grow * D + col + grp * 8;
        const __nv_bfloat16* sl = lsrc + (size_t)grow * D + col + grp * 8;
        bool ok = grow < M;
        cp16(dst,           sh, ok);
        cp16(dst + 16384u,  sl, ok);
    }
}

__global__ void __launch_bounds__(256, 2)
rgcn_gemm_mma(const __nv_bfloat16* __restrict__ aggh,
              const __nv_bfloat16* __restrict__ aggl,
              const __nv_bfloat16* __restrict__ xh,
              const __nv_bfloat16* __restrict__ xl,
              const uint4* __restrict__ bfrag,
              const float* __restrict__ bias,
              float* __restrict__ outf,
              __nv_bfloat16* __restrict__ outh,
              __nv_bfloat16* __restrict__ outl,
              int M) {
    extern __shared__ char smem[];
    uint32_t sbase = smem_u32(smem);
    int t = threadIdx.x;
    int w = t >> 5, lane = t & 31;
    int nwarp = w >> 1;                     // 0..3: 32-col slice
    int row0w = (w & 1) * 64;               // warp's 64-row slice within tile
    int row0  = blockIdx.x * 128;

    float acc[4][4][4];
    #pragma unroll
    for (int mt = 0; mt < 4; mt++)
        #pragma unroll
        for (int nt = 0; nt < 4; nt++)
            #pragma unroll
            for (int j = 0; j < 4; j++) acc[mt][nt][j] = 0.f;

    // prologue: prefetch chunks 0 and 1 (k = 0..63 of agg, 64..127 of agg)
    gemm_prefetch(sbase, 0, aggh, aggl, 0,  row0, M, t); CP_COMMIT();
    gemm_prefetch(sbase, 1, aggh, aggl, 64, row0, M, t); CP_COMMIT();

    int within = lane & 15;
    int half   = lane >> 4;

    #pragma unroll
    for (int kc = 0; kc < 4; kc++) {
        if (kc == 3) { CP_WAIT(0); } else { CP_WAIT(1); }
        __syncthreads();
        int buf = kc & 1;
        uint32_t bufbase = sbase + (uint32_t)buf * 32768u;

        #pragma unroll
        for (int ktl = 0; ktl < 4; ktl++) {
            int grp = ktl * 2 + half;
            uint32_t ahi[4][4], alo[4][4];
            #pragma unroll
            for (int mt = 0; mt < 4; mt++) {
                int row = row0w + mt * 16 + within;
                uint32_t off = bufbase + (uint32_t)row * 128u
                             + (uint32_t)((grp ^ (row & 7)) << 4);
                ldmat_x4(ahi[mt], off);
                ldmat_x4(alo[mt], off + 16384u);
            }
            int ktg = kc * 4 + ktl;
            #pragma unroll
            for (int nt = 0; nt < 4; nt++) {
                uint4 bf = __ldg(&bfrag[((size_t)ktg * 16 + nwarp * 4 + nt) * 32 + lane]);
                #pragma unroll
                for (int mt = 0; mt < 4; mt++) {
                    mma_bf16(acc[mt][nt], ahi[mt], bf.x, bf.y);   // Ah*Bh
                    mma_bf16(acc[mt][nt], ahi[mt], bf.z, bf.w);   // Ah*Bl
                    mma_bf16(acc[mt][nt], alo[mt], bf.x, bf.y);   // Al*Bh
                }
            }
        }
        __syncthreads();
        if (kc < 2) {   // prefetch chunk kc+2 (x planes) into freed buffer
            gemm_prefetch(sbase, buf, xh, xl, kc * 64, row0, M, t);
            CP_COMMIT();
        }
    }

    // ---- epilogue: bias + relu (+ optional bf16 split out) ----
    int tr = lane >> 2, tc = lane & 3;
    int ncol0 = nwarp * 32;
    float2 b2[4];
    #pragma unroll
    for (int nt = 0; nt < 4; nt++)
        b2[nt] = *reinterpret_cast<const float2*>(bias + ncol0 + nt * 8 + tc * 2);

    #pragma unroll
    for (int mt = 0; mt < 4; mt++) {
        int r0 = row0 + row0w + mt * 16 + tr;
        int r1 = r0 + 8;
        #pragma unroll
        for (int nt = 0; nt < 4; nt++) {
            int n = ncol0 + nt * 8 + tc * 2;
            if (r0 < M) {
                float2 v;
                v.x = fmaxf(acc[mt][nt][0] + b2[nt].x, 0.f);
                v.y = fmaxf(acc[mt][nt][1] + b2[nt].y, 0.f);
                *reinterpret_cast<float2*>(outf + (size_t)r0 * D + n) = v;
                if (outh) {
                    uint32_t h, l;
                    split2(v.x, v.y, h, l);
                    *reinterpret_cast<uint32_t*>(outh + (size_t)r0 * D + n) = h;
                    *reinterpret_cast<uint32_t*>(outl + (size_t)r0 * D + n) = l;
                }
            }
            if (r1 < M) {
                float2 v;
                v.x = fmaxf(acc[mt][nt][2] + b2[nt].x, 0.f);
                v.y = fmaxf(acc[mt][nt][3] + b2[nt].y, 0.f);
                *reinterpret_cast<float2*>(outf + (size_t)r1 * D + n) = v;
                if (outh) {
                    uint32_t h, l;
                    split2(v.x, v.y, h, l);
                    *reinterpret_cast<uint32_t*>(outh + (size_t)r1 * D + n) = h;
                    *reinterpret_cast<uint32_t*>(outl + (size_t)r1 * D + n) = l;
                }
            }
        }
    }
}

// ---------------- query -----------------------------------------------------
__global__ void query_kernel(const float* __restrict__ memb,
                             const float* __restrict__ Wq,
                             const float* __restrict__ bq,
                             float* __restrict__ q) {
    int d = threadIdx.x;
    #pragma unroll
    for (int p = 0; p < NP; p++) {
        float s = bq[d];
        #pragma unroll 8
        for (int k = 0; k < 64; k++)
            s += memb[p * 64 + k] * Wq[k * 128 + d];
        q[p * 128 + d] = s;
    }
}

// ---------------- semantic attention ----------------------------------------
__global__ void attn_kernel(const float* __restrict__ sems,
                            const float* __restrict__ q,
                            float* __restrict__ out) {
    int warp = (blockIdx.x * blockDim.x + threadIdx.x) >> 5;
    int lane = threadIdx.x & 31;
    if (warp >= NREG) return;

    float e[NP][4];
    float s[NP];
    #pragma unroll
    for (int p = 0; p < NP; p++) {
        float dotv = 0.f;
        #pragma unroll
        for (int c = 0; c < 4; c++) {
            float v = sems[((size_t)p * NREG + warp) * D + c * 32 + lane];
            e[p][c] = v;
            dotv += v * q[p * 128 + c * 32 + lane];
        }
        #pragma unroll
        for (int o = 16; o > 0; o >>= 1)
            dotv += __shfl_xor_sync(0xffffffffu, dotv, o);
        s[p] = dotv * 0.08838834764831843f;
    }
    float mx = fmaxf(fmaxf(s[0], s[1]), fmaxf(s[2], s[3]));
    float w[NP], sum = 0.f;
    #pragma unroll
    for (int p = 0; p < NP; p++) { w[p] = expf(s[p] - mx); sum += w[p]; }
    float inv = 1.0f / sum;
    #pragma unroll
    for (int c = 0; c < 4; c++) {
        float o = 0.f;
        #pragma unroll
        for (int p = 0; p < NP; p++) o += w[p] * inv * e[p][c];
        out[(size_t)warp * D + c * 32 + lane] = o;
    }
}

// ---------------- launch ----------------------------------------------------
extern "C" void kernel_launch(void* const* d_in, const int* in_sizes, int n_in,
                              void* d_out, int out_size) {
    const float* E          = (const float*)d_in[0];
    const float* memb       = (const float*)d_in[1];
    const float* W_root     = (const float*)d_in[2];
    const float* W_rel      = (const float*)d_in[3];
    const float* b          = (const float*)d_in[4];
    const float* Wq         = (const float*)d_in[5];
    const float* bq         = (const float*)d_in[6];
    const int*   edge_index = (const int*)d_in[7];
    const int*   eids       = (const int*)d_in[8];
    float* out = (float*)d_out;

    float *x0, *x1, *sems, *query;
    int *deg, *bucket;
    uint4* bfrag;
    __nv_bfloat16 *x0h, *x0l, *x1h, *x1l, *aggh, *aggl;
    cudaGetSymbolAddress((void**)&x0,     g_x0);
    cudaGetSymbolAddress((void**)&x1,     g_x1);
    cudaGetSymbolAddress((void**)&sems,   g_sems);
    cudaGetSymbolAddress((void**)&query,  g_query);
    cudaGetSymbolAddress((void**)&deg,    g_deg);
    cudaGetSymbolAddress((void**)&bucket, g_bucket);
    cudaGetSymbolAddress((void**)&bfrag,  g_bfrag);
    cudaGetSymbolAddress((void**)&x0h,    g_x0h);
    cudaGetSymbolAddress((void**)&x0l,    g_x0l);
    cudaGetSymbolAddress((void**)&x1h,    g_x1h);
    cudaGetSymbolAddress((void**)&x1l,    g_x1l);
    cudaGetSymbolAddress((void**)&aggh,   g_aggh);
    cudaGetSymbolAddress((void**)&aggl,   g_aggl);

    cudaFuncSetAttribute(rgcn_gemm_mma,
                         cudaFuncAttributeMaxDynamicSharedMemorySize, GEMM_SMEM);

    const int gatherBlocks = (N_NODES * (D / 4) + 255) / 256;
    const int fillBlocks   = (N_EDGES + 255) / 256;
    const int aggBlocksF   = (N_NODES * 32 + 255) / 256;
    const int aggBlocksH   = (NREG * 32 + 255) / 256;
    const int gemmBlocksF  = (N_NODES + 127) / 128;
    const int gemmBlocksH  = (NREG + 127) / 128;

    for (int p = 0; p < NP; p++) {
        gather_kernel<<<gatherBlocks, 256>>>(E, eids + (size_t)p * N_NODES,
                                             x0, x0h, x0l);

        cudaMemsetAsync(deg, 0, N_NODES * sizeof(int));
        const int* srcp = edge_index + (size_t)p * 2 * N_EDGES;
        const int* dstp = srcp + N_EDGES;
        csr_fill_kernel<<<fillBlocks, 256>>>(srcp, dstp, deg, bucket);

        size_t w0 = (size_t)(p * NL + 0) * D * D;
        size_t w1 = (size_t)(p * NL + 1) * D * D;

        // layer 0 (full width)
        wprep_kernel<<<32, 256>>>(W_rel + w0, W_root + w0, bfrag);
        agg_kernel<<<aggBlocksF, 256>>>(x0, deg, bucket, aggh, aggl, N_NODES);
        rgcn_gemm_mma<<<gemmBlocksF, 256, GEMM_SMEM>>>(
            aggh, aggl, x0h, x0l, bfrag, b + (size_t)(p * NL + 0) * D,
            x1, x1h, x1l, N_NODES);

        // layer 1 (only rows < NREG consumed) -> write straight into sems
        wprep_kernel<<<32, 256>>>(W_rel + w1, W_root + w1, bfrag);
        agg_kernel<<<aggBlocksH, 256>>>(x1, deg, bucket, aggh, aggl, NREG);
        rgcn_gemm_mma<<<gemmBlocksH, 256, GEMM_SMEM>>>(
            aggh, aggl, x1h, x1l, bfrag, b + (size_t)(p * NL + 1) * D,
            sems + (size_t)p * NREG * D, nullptr, nullptr, NREG);
    }

    query_kernel<<<1, 128>>>(memb, Wq, bq, query);
    attn_kernel<<<(NREG + 7) / 8, 256>>>(sems, query, out);
}

// round 15
// speedup vs baseline: 3.6538x; 1.0589x over previous
#include <cuda_runtime.h>
#include <cuda_bf16.h>
#include <cstdint>
#include <cstddef>

#define N_NODES 100000
#define N_EDGES 1600000
#define NREG    50000
#define D       128
#define NP      4
#define NL      2
#define CAP     128

// ---------------- scratch (device globals) ----------------------------------
// bf16 split planes per meta-path (fp32 x is never materialized)
__device__ __nv_bfloat16 g_x0h[NP][(size_t)N_NODES * D];
__device__ __nv_bfloat16 g_x0l[NP][(size_t)N_NODES * D];
__device__ __nv_bfloat16 g_x1h[NP][(size_t)N_NODES * D];
__device__ __nv_bfloat16 g_x1l[NP][(size_t)N_NODES * D];
__device__ __nv_bfloat16 g_aggh[NP][(size_t)N_NODES * D];
__device__ __nv_bfloat16 g_aggl[NP][(size_t)N_NODES * D];
__device__ int   g_deg[NP][N_NODES];
__device__ int   g_bucket[NP][(size_t)N_NODES * CAP];
__device__ float g_sems[(size_t)NP * NREG * D];
__device__ float g_query[NP * D];
// B fragments per (path,layer): [8][kt(16)][nt(16)][lane(32)]
__device__ __align__(16) uint4 g_bfrag[NP * NL][16 * 16 * 32];

// ---------------- helpers ----------------------------------------------------
__device__ __forceinline__ uint32_t smem_u32(const void* p) {
    uint32_t a;
    asm("{ .reg .u64 t; cvta.to.shared.u64 t, %1; cvt.u32.u64 %0, t; }" : "=r"(a) : "l"(p));
    return a;
}
__device__ __forceinline__ uint32_t pack_bf16x2(float lo, float hi) {
    __nv_bfloat162 h;
    h.x = __float2bfloat16(lo);
    h.y = __float2bfloat16(hi);
    return *reinterpret_cast<uint32_t*>(&h);
}
__device__ __forceinline__ void split2(float a, float b, uint32_t& hi, uint32_t& lo) {
    __nv_bfloat16 ha = __float2bfloat16(a);
    __nv_bfloat16 hb = __float2bfloat16(b);
    float fa = __bfloat162float(ha), fb = __bfloat162float(hb);
    hi = pack_bf16x2(fa, fb);
    lo = pack_bf16x2(a - fa, b - fb);
}
// bf16 pair (packed) -> two fp32 (bf16 is the top half of fp32)
__device__ __forceinline__ float bflo(uint32_t v) { return __uint_as_float(v << 16); }
__device__ __forceinline__ float bfhi(uint32_t v) { return __uint_as_float(v & 0xFFFF0000u); }

__device__ __forceinline__ void mma_bf16(float* d, const uint32_t* a, uint32_t b0, uint32_t b1) {
    asm volatile(
        "mma.sync.aligned.m16n8k16.row.col.f32.bf16.bf16.f32 "
        "{%0,%1,%2,%3}, {%4,%5,%6,%7}, {%8,%9}, {%0,%1,%2,%3};"
        : "+f"(d[0]), "+f"(d[1]), "+f"(d[2]), "+f"(d[3])
        : "r"(a[0]), "r"(a[1]), "r"(a[2]), "r"(a[3]), "r"(b0), "r"(b1));
}
__device__ __forceinline__ void ldmat_x4(uint32_t* r, uint32_t addr) {
    asm volatile("ldmatrix.sync.aligned.m8n8.x4.shared.b16 {%0,%1,%2,%3}, [%4];"
                 : "=r"(r[0]), "=r"(r[1]), "=r"(r[2]), "=r"(r[3]) : "r"(addr));
}
__device__ __forceinline__ void cp16(uint32_t dst, const void* src, bool pred) {
    int sz = pred ? 16 : 0;
    asm volatile("cp.async.cg.shared.global [%0], [%1], 16, %2;"
                 :: "r"(dst), "l"(src), "r"(sz));
}
#define CP_COMMIT() asm volatile("cp.async.commit_group;" ::: "memory")
#define CP_WAIT(n)  asm volatile("cp.async.wait_group %0;" :: "n"(n) : "memory")

// ---------------- gather (all paths): planes only ----------------------------
__global__ void gather_all(const float* __restrict__ E,
                           const int* __restrict__ eids_base,
                           __nv_bfloat16* __restrict__ xh_base,
                           __nv_bfloat16* __restrict__ xl_base) {
    int i = blockIdx.x * blockDim.x + threadIdx.x;
    if (i >= N_NODES * (D / 4)) return;
    int p = blockIdx.y;
    int n = i >> 5, c = i & 31;
    int e = eids_base[(size_t)p * N_NODES + n];
    float4 v = reinterpret_cast<const float4*>(E)[(size_t)e * 32 + c];
    uint2 h2, l2;
    split2(v.x, v.y, h2.x, l2.x);
    split2(v.z, v.w, h2.y, l2.y);
    size_t off = (size_t)p * N_NODES * D;
    reinterpret_cast<uint2*>(xh_base + off)[(size_t)n * 32 + c] = h2;
    reinterpret_cast<uint2*>(xl_base + off)[(size_t)n * 32 + c] = l2;
}

// ---------------- bucket-CSR build (all paths) -------------------------------
__global__ void csr_all(const int* __restrict__ edge_index,
                        int* __restrict__ deg_base,
                        int* __restrict__ bucket_base) {
    int i = blockIdx.x * blockDim.x + threadIdx.x;
    if (i >= N_EDGES) return;
    int p = blockIdx.y;
    const int* src = edge_index + (size_t)p * 2 * N_EDGES;
    const int* dst = src + N_EDGES;
    int d = dst[i];
    int pos = atomicAdd(deg_base + (size_t)p * N_NODES + d, 1);
    if (pos < CAP) bucket_base[(size_t)p * N_NODES * CAP + (size_t)d * CAP + pos] = src[i];
}

// ---------------- pull aggregation from planes (all paths) -------------------
__global__ void agg_all(const __nv_bfloat16* __restrict__ xh_base,
                        const __nv_bfloat16* __restrict__ xl_base,
                        const int* __restrict__ deg_base,
                        const int* __restrict__ bucket_base,
                        __nv_bfloat16* __restrict__ aggh_base,
                        __nv_bfloat16* __restrict__ aggl_base,
                        int nNodes) {
    int warp = (blockIdx.x * blockDim.x + threadIdx.x) >> 5;
    int lane = threadIdx.x & 31;
    if (warp >= nNodes) return;
    int p = blockIdx.y;
    size_t poff = (size_t)p * N_NODES * D;
    const uint2* h4 = reinterpret_cast<const uint2*>(xh_base + poff);
    const uint2* l4 = reinterpret_cast<const uint2*>(xl_base + poff);

    int dg = deg_base[(size_t)p * N_NODES + warp];
    int n  = dg < CAP ? dg : CAP;
    const int* b = bucket_base + (size_t)p * N_NODES * CAP + (size_t)warp * CAP;

    float a0 = 0.f, a1 = 0.f, a2 = 0.f, a3 = 0.f;
    int e = 0;
    for (; e + 2 <= n; e += 2) {
        int s0 = b[e], s1 = b[e + 1];
        uint2 h0 = h4[(size_t)s0 * 32 + lane];
        uint2 l0 = l4[(size_t)s0 * 32 + lane];
        uint2 h1 = h4[(size_t)s1 * 32 + lane];
        uint2 l1 = l4[(size_t)s1 * 32 + lane];
        a0 += (bflo(h0.x) + bflo(l0.x)) + (bflo(h1.x) + bflo(l1.x));
        a1 += (bfhi(h0.x) + bfhi(l0.x)) + (bfhi(h1.x) + bfhi(l1.x));
        a2 += (bflo(h0.y) + bflo(l0.y)) + (bflo(h1.y) + bflo(l1.y));
        a3 += (bfhi(h0.y) + bfhi(l0.y)) + (bfhi(h1.y) + bfhi(l1.y));
    }
    if (e < n) {
        int s0 = b[e];
        uint2 h0 = h4[(size_t)s0 * 32 + lane];
        uint2 l0 = l4[(size_t)s0 * 32 + lane];
        a0 += bflo(h0.x) + bflo(l0.x);
        a1 += bfhi(h0.x) + bfhi(l0.x);
        a2 += bflo(h0.y) + bflo(l0.y);
        a3 += bfhi(h0.y) + bfhi(l0.y);
    }
    float rinv = 1.0f / fmaxf((float)dg, 1.0f);
    a0 *= rinv; a1 *= rinv; a2 *= rinv; a3 *= rinv;
    uint2 h2, l2;
    split2(a0, a1, h2.x, l2.x);
    split2(a2, a3, h2.y, l2.y);
    reinterpret_cast<uint2*>(aggh_base + poff)[(size_t)warp * 32 + lane] = h2;
    reinterpret_cast<uint2*>(aggl_base + poff)[(size_t)warp * 32 + lane] = l2;
}

// ---------------- weight prep: all 8 tables ----------------------------------
__global__ void wprep_all(const float* __restrict__ W_rel,
                          const float* __restrict__ W_root,
                          uint4* __restrict__ bfrag_base) {
    int i = blockIdx.x * blockDim.x + threadIdx.x;
    if (i >= 16 * 16 * 32) return;
    int tbl = blockIdx.y;                  // 0..7 == p*NL+l
    const float* Wm = W_rel  + (size_t)tbl * D * D;
    const float* Wr = W_root + (size_t)tbl * D * D;

    int lane = i & 31;
    int nt   = (i >> 5) & 15;
    int kt   = i >> 9;
    int n  = nt * 8 + (lane >> 2);
    int k0 = kt * 16 + (lane & 3) * 2;

    float w[4];
    #pragma unroll
    for (int j = 0; j < 4; j++) {
        int k = k0 + (j >> 1) * 8 + (j & 1);
        w[j] = (k < 128) ? Wm[k * 128 + n] : Wr[(k - 128) * 128 + n];
    }
    uint4 r;
    split2(w[0], w[1], r.x, r.z);
    split2(w[2], w[3], r.y, r.w);
    bfrag_base[(size_t)tbl * 8192 + i] = r;
}

// ---------------- mma.sync RGCN GEMM (batched over paths) --------------------
#define GEMM_SMEM 65536

__device__ __forceinline__ void gemm_prefetch(
    uint32_t sbase, int buf,
    const __nv_bfloat16* __restrict__ hsrc,
    const __nv_bfloat16* __restrict__ lsrc,
    int col, int row0, int M, int t) {
    int grp = t & 7;
    #pragma unroll
    for (int i = 0; i < 4; i++) {
        int row  = (t >> 3) + i * 32;
        int grow = row0 + row;
        uint32_t dst = sbase + (uint32_t)buf * 32768u + (uint32_t)row * 128u
                     + (uint32_t)((grp ^ (row & 7)) << 4);
        const __nv_bfloat16* sh = hsrc + (size_t)grow * D + col + grp * 8;
        const __nv_bfloat16* sl = lsrc + (size_t)grow * D + col + grp * 8;
        bool ok = grow < M;
        cp16(dst,          sh, ok);
        cp16(dst + 16384u, sl, ok);
    }
}

__global__ void __launch_bounds__(256, 2)
gemm_all(const __nv_bfloat16* __restrict__ aggh_base,
         const __nv_bfloat16* __restrict__ aggl_base,
         const __nv_bfloat16* __restrict__ xh_base,
         const __nv_bfloat16* __restrict__ xl_base,
         const uint4* __restrict__ bfrag_base,
         const float* __restrict__ bias_base,
         float* __restrict__ sems_base,          // non-null => layer 1
         __nv_bfloat16* __restrict__ outh_base,  // non-null => layer 0
         __nv_bfloat16* __restrict__ outl_base,
         int M, int layer) {
    extern __shared__ char smem[];
    uint32_t sbase = smem_u32(smem);
    int p = blockIdx.y;
    size_t poff = (size_t)p * N_NODES * D;
    const __nv_bfloat16* aggh = aggh_base + poff;
    const __nv_bfloat16* aggl = aggl_base + poff;
    const __nv_bfloat16* xh   = xh_base + poff;
    const __nv_bfloat16* xl   = xl_base + poff;
    const uint4* bfrag = bfrag_base + (size_t)(p * NL + layer) * 8192;
    const float* bias  = bias_base + (size_t)(p * NL + layer) * D;
    float* outf = sems_base ? sems_base + (size_t)p * NREG * D : nullptr;
    __nv_bfloat16* outh = outh_base ? outh_base + poff : nullptr;
    __nv_bfloat16* outl = outl_base ? outl_base + poff : nullptr;

    int t = threadIdx.x;
    int w = t >> 5, lane = t & 31;
    int nwarp = w >> 1;
    int row0w = (w & 1) * 64;
    int row0  = blockIdx.x * 128;

    float acc[4][4][4];
    #pragma unroll
    for (int mt = 0; mt < 4; mt++)
        #pragma unroll
        for (int nt = 0; nt < 4; nt++)
            #pragma unroll
            for (int j = 0; j < 4; j++) acc[mt][nt][j] = 0.f;

    gemm_prefetch(sbase, 0, aggh, aggl, 0,  row0, M, t); CP_COMMIT();
    gemm_prefetch(sbase, 1, aggh, aggl, 64, row0, M, t); CP_COMMIT();

    int within = lane & 15;
    int half   = lane >> 4;

    #pragma unroll
    for (int kc = 0; kc < 4; kc++) {
        if (kc == 3) { CP_WAIT(0); } else { CP_WAIT(1); }
        __syncthreads();
        int buf = kc & 1;
        uint32_t bufbase = sbase + (uint32_t)buf * 32768u;

        #pragma unroll
        for (int ktl = 0; ktl < 4; ktl++) {
            int grp = ktl * 2 + half;
            uint32_t ahi[4][4], alo[4][4];
            #pragma unroll
            for (int mt = 0; mt < 4; mt++) {
                int row = row0w + mt * 16 + within;
                uint32_t off = bufbase + (uint32_t)row * 128u
                             + (uint32_t)((grp ^ (row & 7)) << 4);
                ldmat_x4(ahi[mt], off);
                ldmat_x4(alo[mt], off + 16384u);
            }
            int ktg = kc * 4 + ktl;
            #pragma unroll
            for (int nt = 0; nt < 4; nt++) {
                uint4 bf = __ldg(&bfrag[((size_t)ktg * 16 + nwarp * 4 + nt) * 32 + lane]);
                #pragma unroll
                for (int mt = 0; mt < 4; mt++) {
                    mma_bf16(acc[mt][nt], ahi[mt], bf.x, bf.y);
                    mma_bf16(acc[mt][nt], ahi[mt], bf.z, bf.w);
                    mma_bf16(acc[mt][nt], alo[mt], bf.x, bf.y);
                }
            }
        }
        __syncthreads();
        if (kc < 2) {
            gemm_prefetch(sbase, buf, xh, xl, kc * 64, row0, M, t);
            CP_COMMIT();
        }
    }

    // ---- epilogue: bias + relu; layer0 -> split planes, layer1 -> fp32 sems ----
    int tr = lane >> 2, tc = lane & 3;
    int ncol0 = nwarp * 32;
    float2 b2[4];
    #pragma unroll
    for (int nt = 0; nt < 4; nt++)
        b2[nt] = *reinterpret_cast<const float2*>(bias + ncol0 + nt * 8 + tc * 2);

    #pragma unroll
    for (int mt = 0; mt < 4; mt++) {
        int r0 = row0 + row0w + mt * 16 + tr;
        int r1 = r0 + 8;
        #pragma unroll
        for (int nt = 0; nt < 4; nt++) {
            int n = ncol0 + nt * 8 + tc * 2;
            #pragma unroll
            for (int hh = 0; hh < 2; hh++) {
                int r = hh ? r1 : r0;
                if (r >= M) continue;
                float vx = fmaxf(acc[mt][nt][hh * 2 + 0] + b2[nt].x, 0.f);
                float vy = fmaxf(acc[mt][nt][hh * 2 + 1] + b2[nt].y, 0.f);
                if (outf)
                    *reinterpret_cast<float2*>(outf + (size_t)r * D + n) = make_float2(vx, vy);
                if (outh) {
                    uint32_t h, l;
                    split2(vx, vy, h, l);
                    *reinterpret_cast<uint32_t*>(outh + (size_t)r * D + n) = h;
                    *reinterpret_cast<uint32_t*>(outl + (size_t)r * D + n) = l;
                }
            }
        }
    }
}

// ---------------- query -----------------------------------------------------
__global__ void query_kernel(const float* __restrict__ memb,
                             const float* __restrict__ Wq,
                             const float* __restrict__ bq,
                             float* __restrict__ q) {
    int d = threadIdx.x;
    #pragma unroll
    for (int p = 0; p < NP; p++) {
        float s = bq[d];
        #pragma unroll 8
        for (int k = 0; k < 64; k++)
            s += memb[p * 64 + k] * Wq[k * 128 + d];
        q[p * 128 + d] = s;
    }
}

// ---------------- semantic attention ----------------------------------------
__global__ void attn_kernel(const float* __restrict__ sems,
                            const float* __restrict__ q,
                            float* __restrict__ out) {
    int warp = (blockIdx.x * blockDim.x + threadIdx.x) >> 5;
    int lane = threadIdx.x & 31;
    if (warp >= NREG) return;

    float e[NP][4];
    float s[NP];
    #pragma unroll
    for (int p = 0; p < NP; p++) {
        float dotv = 0.f;
        #pragma unroll
        for (int c = 0; c < 4; c++) {
            float v = sems[((size_t)p * NREG + warp) * D + c * 32 + lane];
            e[p][c] = v;
            dotv += v * q[p * 128 + c * 32 + lane];
        }
        #pragma unroll
        for (int o = 16; o > 0; o >>= 1)
            dotv += __shfl_xor_sync(0xffffffffu, dotv, o);
        s[p] = dotv * 0.08838834764831843f;
    }
    float mx = fmaxf(fmaxf(s[0], s[1]), fmaxf(s[2], s[3]));
    float w[NP], sum = 0.f;
    #pragma unroll
    for (int p = 0; p < NP; p++) { w[p] = expf(s[p] - mx); sum += w[p]; }
    float inv = 1.0f / sum;
    #pragma unroll
    for (int c = 0; c < 4; c++) {
        float o = 0.f;
        #pragma unroll
        for (int p = 0; p < NP; p++) o += w[p] * inv * e[p][c];
        out[(size_t)warp * D + c * 32 + lane] = o;
    }
}

// ---------------- launch ----------------------------------------------------
extern "C" void kernel_launch(void* const* d_in, const int* in_sizes, int n_in,
                              void* d_out, int out_size) {
    const float* E          = (const float*)d_in[0];
    const float* memb       = (const float*)d_in[1];
    const float* W_root     = (const float*)d_in[2];
    const float* W_rel      = (const float*)d_in[3];
    const float* b          = (const float*)d_in[4];
    const float* Wq         = (const float*)d_in[5];
    const float* bq         = (const float*)d_in[6];
    const int*   edge_index = (const int*)d_in[7];
    const int*   eids       = (const int*)d_in[8];
    float* out = (float*)d_out;

    float *sems, *query;
    int *deg, *bucket;
    uint4* bfrag;
    __nv_bfloat16 *x0h, *x0l, *x1h, *x1l, *aggh, *aggl;
    cudaGetSymbolAddress((void**)&sems,   g_sems);
    cudaGetSymbolAddress((void**)&query,  g_query);
    cudaGetSymbolAddress((void**)&deg,    g_deg);
    cudaGetSymbolAddress((void**)&bucket, g_bucket);
    cudaGetSymbolAddress((void**)&bfrag,  g_bfrag);
    cudaGetSymbolAddress((void**)&x0h,    g_x0h);
    cudaGetSymbolAddress((void**)&x0l,    g_x0l);
    cudaGetSymbolAddress((void**)&x1h,    g_x1h);
    cudaGetSymbolAddress((void**)&x1l,    g_x1l);
    cudaGetSymbolAddress((void**)&aggh,   g_aggh);
    cudaGetSymbolAddress((void**)&aggl,   g_aggl);

    cudaFuncSetAttribute(gemm_all,
                         cudaFuncAttributeMaxDynamicSharedMemorySize, GEMM_SMEM);

    dim3 gatherGrid((N_NODES * (D / 4) + 255) / 256, NP);
    dim3 csrGrid((N_EDGES + 255) / 256, NP);
    dim3 wprepGrid(32, NP * NL);
    dim3 agg0Grid((N_NODES * 32 + 255) / 256, NP);
    dim3 agg1Grid((NREG * 32 + 255) / 256, NP);
    dim3 gemm0Grid((N_NODES + 127) / 128, NP);
    dim3 gemm1Grid((NREG + 127) / 128, NP);

    // phase 0: independent prep
    cudaMemsetAsync(deg, 0, (size_t)NP * N_NODES * sizeof(int));
    gather_all<<<gatherGrid, 256>>>(E, eids, x0h, x0l);
    csr_all<<<csrGrid, 256>>>(edge_index, deg, bucket);
    wprep_all<<<wprepGrid, 256>>>(W_rel, W_root, bfrag);

    // layer 0 (full width): agg + gemm -> x1 planes
    agg_all<<<agg0Grid, 256>>>(x0h, x0l, deg, bucket, aggh, aggl, N_NODES);
    gemm_all<<<gemm0Grid, 256, GEMM_SMEM>>>(
        aggh, aggl, x0h, x0l, bfrag, b,
        nullptr, x1h, x1l, N_NODES, 0);

    // layer 1 (rows < NREG): agg + gemm -> fp32 sems
    agg_all<<<agg1Grid, 256>>>(x1h, x1l, deg, bucket, aggh, aggl, NREG);
    gemm_all<<<gemm1Grid, 256, GEMM_SMEM>>>(
        aggh, aggl, x1h, x1l, bfrag, b,
        sems, nullptr, nullptr, NREG, 1);

    query_kernel<<<1, 128>>>(memb, Wq, bq, query);
    attn_kernel<<<(NREG + 7) / 8, 256>>>(sems, query, out);
}

// round 16
// speedup vs baseline: 3.7023x; 1.0133x over previous
#include <cuda_runtime.h>
#include <cuda_bf16.h>
#include <cstdint>
#include <cstddef>

#define N_NODES 100000
#define N_EDGES 1600000
#define NREG    50000
#define D       128
#define NP      4
#define NL      2
#define CAP     128

// ---------------- scratch (device globals) ----------------------------------
__device__ __nv_bfloat16 g_x0h[NP][(size_t)N_NODES * D];
__device__ __nv_bfloat16 g_x0l[NP][(size_t)N_NODES * D];
__device__ __nv_bfloat16 g_x1h[NP][(size_t)N_NODES * D];
__device__ __nv_bfloat16 g_x1l[NP][(size_t)N_NODES * D];
__device__ __nv_bfloat16 g_aggh[NP][(size_t)N_NODES * D];
__device__ __nv_bfloat16 g_aggl[NP][(size_t)N_NODES * D];
__device__ int   g_deg[NP][N_NODES];
__device__ int   g_bucket[NP][(size_t)N_NODES * CAP];
__device__ float g_sems[(size_t)NP * NREG * D];
__device__ float g_query[NP * D];
__device__ __align__(16) uint4 g_bfrag[NP * NL][16 * 16 * 32];

// ---------------- helpers ----------------------------------------------------
__device__ __forceinline__ uint32_t smem_u32(const void* p) {
    uint32_t a;
    asm("{ .reg .u64 t; cvta.to.shared.u64 t, %1; cvt.u32.u64 %0, t; }" : "=r"(a) : "l"(p));
    return a;
}
__device__ __forceinline__ uint32_t pack_bf16x2(float lo, float hi) {
    __nv_bfloat162 h;
    h.x = __float2bfloat16(lo);
    h.y = __float2bfloat16(hi);
    return *reinterpret_cast<uint32_t*>(&h);
}
__device__ __forceinline__ void split2(float a, float b, uint32_t& hi, uint32_t& lo) {
    __nv_bfloat16 ha = __float2bfloat16(a);
    __nv_bfloat16 hb = __float2bfloat16(b);
    float fa = __bfloat162float(ha), fb = __bfloat162float(hb);
    hi = pack_bf16x2(fa, fb);
    lo = pack_bf16x2(a - fa, b - fb);
}
__device__ __forceinline__ float bflo(uint32_t v) { return __uint_as_float(v << 16); }
__device__ __forceinline__ float bfhi(uint32_t v) { return __uint_as_float(v & 0xFFFF0000u); }

__device__ __forceinline__ void mma_bf16(float* d, const uint32_t* a, uint32_t b0, uint32_t b1) {
    asm volatile(
        "mma.sync.aligned.m16n8k16.row.col.f32.bf16.bf16.f32 "
        "{%0,%1,%2,%3}, {%4,%5,%6,%7}, {%8,%9}, {%0,%1,%2,%3};"
        : "+f"(d[0]), "+f"(d[1]), "+f"(d[2]), "+f"(d[3])
        : "r"(a[0]), "r"(a[1]), "r"(a[2]), "r"(a[3]), "r"(b0), "r"(b1));
}
__device__ __forceinline__ void ldmat_x4(uint32_t* r, uint32_t addr) {
    asm volatile("ldmatrix.sync.aligned.m8n8.x4.shared.b16 {%0,%1,%2,%3}, [%4];"
                 : "=r"(r[0]), "=r"(r[1]), "=r"(r[2]), "=r"(r[3]) : "r"(addr));
}
__device__ __forceinline__ void cp16(uint32_t dst, const void* src, bool pred) {
    int sz = pred ? 16 : 0;
    asm volatile("cp.async.cg.shared.global [%0], [%1], 16, %2;"
                 :: "r"(dst), "l"(src), "r"(sz));
}
#define CP_COMMIT() asm volatile("cp.async.commit_group;" ::: "memory")
#define CP_WAIT(n)  asm volatile("cp.async.wait_group %0;" :: "n"(n) : "memory")

// ---------------- gather (paths interleaved: E table shared in L2) -----------
__global__ void gather_all(const float* __restrict__ E,
                           const int* __restrict__ eids_base,
                           __nv_bfloat16* __restrict__ xh_base,
                           __nv_bfloat16* __restrict__ xl_base) {
    int i = blockIdx.x * blockDim.x + threadIdx.x;
    if (i >= N_NODES * (D / 4)) return;
    int p = blockIdx.y;
    int n = i >> 5, c = i & 31;
    int e = eids_base[(size_t)p * N_NODES + n];
    float4 v = reinterpret_cast<const float4*>(E)[(size_t)e * 32 + c];
    uint2 h2, l2;
    split2(v.x, v.y, h2.x, l2.x);
    split2(v.z, v.w, h2.y, l2.y);
    size_t off = (size_t)p * N_NODES * D;
    reinterpret_cast<uint2*>(xh_base + off)[(size_t)n * 32 + c] = h2;
    reinterpret_cast<uint2*>(xl_base + off)[(size_t)n * 32 + c] = l2;
}

// ---------------- bucket-CSR build: path-major, 4-edge ILP -------------------
#define CSR_EPT 4
__global__ void csr_all(const int* __restrict__ edge_index,
                        int* __restrict__ deg_base,
                        int* __restrict__ bucket_base,
                        int edgeBlocks) {
    int p   = blockIdx.x / edgeBlocks;
    int blk = blockIdx.x % edgeBlocks;
    int base = blk * 256 * CSR_EPT + threadIdx.x;
    const int* src = edge_index + (size_t)p * 2 * N_EDGES;
    const int* dst = src + N_EDGES;
    int* deg = deg_base + (size_t)p * N_NODES;
    int* bucket = bucket_base + (size_t)p * N_NODES * CAP;

    int d[CSR_EPT], s[CSR_EPT];
    bool ok[CSR_EPT];
    #pragma unroll
    for (int j = 0; j < CSR_EPT; j++) {
        int i = base + j * 256;
        ok[j] = i < N_EDGES;
        d[j] = ok[j] ? dst[i] : 0;
        s[j] = ok[j] ? src[i] : 0;
    }
    int pos[CSR_EPT];
    #pragma unroll
    for (int j = 0; j < CSR_EPT; j++)
        if (ok[j]) pos[j] = atomicAdd(deg + d[j], 1);
    #pragma unroll
    for (int j = 0; j < CSR_EPT; j++)
        if (ok[j] && pos[j] < CAP) bucket[(size_t)d[j] * CAP + pos[j]] = s[j];
}

// ---------------- pull aggregation: path-major ordering ----------------------
__global__ void agg_all(const __nv_bfloat16* __restrict__ xh_base,
                        const __nv_bfloat16* __restrict__ xl_base,
                        const int* __restrict__ deg_base,
                        const int* __restrict__ bucket_base,
                        __nv_bfloat16* __restrict__ aggh_base,
                        __nv_bfloat16* __restrict__ aggl_base,
                        int nNodes, int aggBlocks) {
    int p   = blockIdx.x / aggBlocks;
    int blk = blockIdx.x % aggBlocks;
    int warp = (blk * 256 + threadIdx.x) >> 5;
    int lane = threadIdx.x & 31;
    if (warp >= nNodes) return;
    size_t poff = (size_t)p * N_NODES * D;
    const uint2* h4 = reinterpret_cast<const uint2*>(xh_base + poff);
    const uint2* l4 = reinterpret_cast<const uint2*>(xl_base + poff);

    int dg = deg_base[(size_t)p * N_NODES + warp];
    int n  = dg < CAP ? dg : CAP;
    const int* b = bucket_base + (size_t)p * N_NODES * CAP + (size_t)warp * CAP;

    float a0 = 0.f, a1 = 0.f, a2 = 0.f, a3 = 0.f;
    int e = 0;
    for (; e + 2 <= n; e += 2) {
        int s0 = b[e], s1 = b[e + 1];
        uint2 h0 = h4[(size_t)s0 * 32 + lane];
        uint2 l0 = l4[(size_t)s0 * 32 + lane];
        uint2 h1 = h4[(size_t)s1 * 32 + lane];
        uint2 l1 = l4[(size_t)s1 * 32 + lane];
        a0 += (bflo(h0.x) + bflo(l0.x)) + (bflo(h1.x) + bflo(l1.x));
        a1 += (bfhi(h0.x) + bfhi(l0.x)) + (bfhi(h1.x) + bfhi(l1.x));
        a2 += (bflo(h0.y) + bflo(l0.y)) + (bflo(h1.y) + bflo(l1.y));
        a3 += (bfhi(h0.y) + bfhi(l0.y)) + (bfhi(h1.y) + bfhi(l1.y));
    }
    if (e < n) {
        int s0 = b[e];
        uint2 h0 = h4[(size_t)s0 * 32 + lane];
        uint2 l0 = l4[(size_t)s0 * 32 + lane];
        a0 += bflo(h0.x) + bflo(l0.x);
        a1 += bfhi(h0.x) + bfhi(l0.x);
        a2 += bflo(h0.y) + bflo(l0.y);
        a3 += bfhi(h0.y) + bfhi(l0.y);
    }
    float rinv = 1.0f / fmaxf((float)dg, 1.0f);
    a0 *= rinv; a1 *= rinv; a2 *= rinv; a3 *= rinv;
    uint2 h2, l2;
    split2(a0, a1, h2.x, l2.x);
    split2(a2, a3, h2.y, l2.y);
    reinterpret_cast<uint2*>(aggh_base + poff)[(size_t)warp * 32 + lane] = h2;
    reinterpret_cast<uint2*>(aggl_base + poff)[(size_t)warp * 32 + lane] = l2;
}

// ---------------- weight prep ------------------------------------------------
__global__ void wprep_all(const float* __restrict__ W_rel,
                          const float* __restrict__ W_root,
                          uint4* __restrict__ bfrag_base) {
    int i = blockIdx.x * blockDim.x + threadIdx.x;
    if (i >= 16 * 16 * 32) return;
    int tbl = blockIdx.y;
    const float* Wm = W_rel  + (size_t)tbl * D * D;
    const float* Wr = W_root + (size_t)tbl * D * D;

    int lane = i & 31;
    int nt   = (i >> 5) & 15;
    int kt   = i >> 9;
    int n  = nt * 8 + (lane >> 2);
    int k0 = kt * 16 + (lane & 3) * 2;

    float w[4];
    #pragma unroll
    for (int j = 0; j < 4; j++) {
        int k = k0 + (j >> 1) * 8 + (j & 1);
        w[j] = (k < 128) ? Wm[k * 128 + n] : Wr[(k - 128) * 128 + n];
    }
    uint4 r;
    split2(w[0], w[1], r.x, r.z);
    split2(w[2], w[3], r.y, r.w);
    bfrag_base[(size_t)tbl * 8192 + i] = r;
}

// ---------------- mma.sync RGCN GEMM (path-major) ----------------------------
#define GEMM_SMEM 65536

__device__ __forceinline__ void gemm_prefetch(
    uint32_t sbase, int buf,
    const __nv_bfloat16* __restrict__ hsrc,
    const __nv_bfloat16* __restrict__ lsrc,
    int col, int row0, int M, int t) {
    int grp = t & 7;
    #pragma unroll
    for (int i = 0; i < 4; i++) {
        int row  = (t >> 3) + i * 32;
        int grow = row0 + row;
        uint32_t dst = sbase + (uint32_t)buf * 32768u + (uint32_t)row * 128u
                     + (uint32_t)((grp ^ (row & 7)) << 4);
        const __nv_bfloat16* sh = hsrc + (size_t)grow * D + col + grp * 8;
        const __nv_bfloat16* sl = lsrc + (size_t)grow * D + col + grp * 8;
        bool ok = grow < M;
        cp16(dst,          sh, ok);
        cp16(dst + 16384u, sl, ok);
    }
}

__global__ void __launch_bounds__(256, 2)
gemm_all(const __nv_bfloat16* __restrict__ aggh_base,
         const __nv_bfloat16* __restrict__ aggl_base,
         const __nv_bfloat16* __restrict__ xh_base,
         const __nv_bfloat16* __restrict__ xl_base,
         const uint4* __restrict__ bfrag_base,
         const float* __restrict__ bias_base,
         float* __restrict__ sems_base,
         __nv_bfloat16* __restrict__ outh_base,
         __nv_bfloat16* __restrict__ outl_base,
         int M, int layer, int mBlocks) {
    extern __shared__ char smem[];
    uint32_t sbase = smem_u32(smem);
    int p    = blockIdx.x / mBlocks;
    int mblk = blockIdx.x % mBlocks;
    size_t poff = (size_t)p * N_NODES * D;
    const __nv_bfloat16* aggh = aggh_base + poff;
    const __nv_bfloat16* aggl = aggl_base + poff;
    const __nv_bfloat16* xh   = xh_base + poff;
    const __nv_bfloat16* xl   = xl_base + poff;
    const uint4* bfrag = bfrag_base + (size_t)(p * NL + layer) * 8192;
    const float* bias  = bias_base + (size_t)(p * NL + layer) * D;
    float* outf = sems_base ? sems_base + (size_t)p * NREG * D : nullptr;
    __nv_bfloat16* outh = outh_base ? outh_base + poff : nullptr;
    __nv_bfloat16* outl = outl_base ? outl_base + poff : nullptr;

    int t = threadIdx.x;
    int w = t >> 5, lane = t & 31;
    int nwarp = w >> 1;
    int row0w = (w & 1) * 64;
    int row0  = mblk * 128;

    float acc[4][4][4];
    #pragma unroll
    for (int mt = 0; mt < 4; mt++)
        #pragma unroll
        for (int nt = 0; nt < 4; nt++)
            #pragma unroll
            for (int j = 0; j < 4; j++) acc[mt][nt][j] = 0.f;

    gemm_prefetch(sbase, 0, aggh, aggl, 0,  row0, M, t); CP_COMMIT();
    gemm_prefetch(sbase, 1, aggh, aggl, 64, row0, M, t); CP_COMMIT();

    int within = lane & 15;
    int half   = lane >> 4;

    #pragma unroll
    for (int kc = 0; kc < 4; kc++) {
        if (kc == 3) { CP_WAIT(0); } else { CP_WAIT(1); }
        __syncthreads();
        int buf = kc & 1;
        uint32_t bufbase = sbase + (uint32_t)buf * 32768u;

        #pragma unroll
        for (int ktl = 0; ktl < 4; ktl++) {
            int grp = ktl * 2 + half;
            uint32_t ahi[4][4], alo[4][4];
            #pragma unroll
            for (int mt = 0; mt < 4; mt++) {
                int row = row0w + mt * 16 + within;
                uint32_t off = bufbase + (uint32_t)row * 128u
                             + (uint32_t)((grp ^ (row & 7)) << 4);
                ldmat_x4(ahi[mt], off);
                ldmat_x4(alo[mt], off + 16384u);
            }
            int ktg = kc * 4 + ktl;
            #pragma unroll
            for (int nt = 0; nt < 4; nt++) {
                uint4 bf = __ldg(&bfrag[((size_t)ktg * 16 + nwarp * 4 + nt) * 32 + lane]);
                #pragma unroll
                for (int mt = 0; mt < 4; mt++) {
                    mma_bf16(acc[mt][nt], ahi[mt], bf.x, bf.y);
                    mma_bf16(acc[mt][nt], ahi[mt], bf.z, bf.w);
                    mma_bf16(acc[mt][nt], alo[mt], bf.x, bf.y);
                }
            }
        }
        __syncthreads();
        if (kc < 2) {
            gemm_prefetch(sbase, buf, xh, xl, kc * 64, row0, M, t);
            CP_COMMIT();
        }
    }

    int tr = lane >> 2, tc = lane & 3;
    int ncol0 = nwarp * 32;
    float2 b2[4];
    #pragma unroll
    for (int nt = 0; nt < 4; nt++)
        b2[nt] = *reinterpret_cast<const float2*>(bias + ncol0 + nt * 8 + tc * 2);

    #pragma unroll
    for (int mt = 0; mt < 4; mt++) {
        int r0 = row0 + row0w + mt * 16 + tr;
        #pragma unroll
        for (int nt = 0; nt < 4; nt++) {
            int n = ncol0 + nt * 8 + tc * 2;
            #pragma unroll
            for (int hh = 0; hh < 2; hh++) {
                int r = r0 + hh * 8;
                if (r >= M) continue;
                float vx = fmaxf(acc[mt][nt][hh * 2 + 0] + b2[nt].x, 0.f);
                float vy = fmaxf(acc[mt][nt][hh * 2 + 1] + b2[nt].y, 0.f);
                if (outf)
                    *reinterpret_cast<float2*>(outf + (size_t)r * D + n) = make_float2(vx, vy);
                if (outh) {
                    uint32_t h, l;
                    split2(vx, vy, h, l);
                    *reinterpret_cast<uint32_t*>(outh + (size_t)r * D + n) = h;
                    *reinterpret_cast<uint32_t*>(outl + (size_t)r * D + n) = l;
                }
            }
        }
    }
}

// ---------------- query -----------------------------------------------------
__global__ void query_kernel(const float* __restrict__ memb,
                             const float* __restrict__ Wq,
                             const float* __restrict__ bq,
                             float* __restrict__ q) {
    int d = threadIdx.x;
    #pragma unroll
    for (int p = 0; p < NP; p++) {
        float s = bq[d];
        #pragma unroll 8
        for (int k = 0; k < 64; k++)
            s += memb[p * 64 + k] * Wq[k * 128 + d];
        q[p * 128 + d] = s;
    }
}

// ---------------- semantic attention ----------------------------------------
__global__ void attn_kernel(const float* __restrict__ sems,
                            const float* __restrict__ q,
                            float* __restrict__ out) {
    int warp = (blockIdx.x * blockDim.x + threadIdx.x) >> 5;
    int lane = threadIdx.x & 31;
    if (warp >= NREG) return;

    float e[NP][4];
    float s[NP];
    #pragma unroll
    for (int p = 0; p < NP; p++) {
        float dotv = 0.f;
        #pragma unroll
        for (int c = 0; c < 4; c++) {
            float v = sems[((size_t)p * NREG + warp) * D + c * 32 + lane];
            e[p][c] = v;
            dotv += v * q[p * 128 + c * 32 + lane];
        }
        #pragma unroll
        for (int o = 16; o > 0; o >>= 1)
            dotv += __shfl_xor_sync(0xffffffffu, dotv, o);
        s[p] = dotv * 0.08838834764831843f;
    }
    float mx = fmaxf(fmaxf(s[0], s[1]), fmaxf(s[2], s[3]));
    float w[NP], sum = 0.f;
    #pragma unroll
    for (int p = 0; p < NP; p++) { w[p] = expf(s[p] - mx); sum += w[p]; }
    float inv = 1.0f / sum;
    #pragma unroll
    for (int c = 0; c < 4; c++) {
        float o = 0.f;
        #pragma unroll
        for (int p = 0; p < NP; p++) o += w[p] * inv * e[p][c];
        out[(size_t)warp * D + c * 32 + lane] = o;
    }
}

// ---------------- launch ----------------------------------------------------
extern "C" void kernel_launch(void* const* d_in, const int* in_sizes, int n_in,
                              void* d_out, int out_size) {
    const float* E          = (const float*)d_in[0];
    const float* memb       = (const float*)d_in[1];
    const float* W_root     = (const float*)d_in[2];
    const float* W_rel      = (const float*)d_in[3];
    const float* b          = (const float*)d_in[4];
    const float* Wq         = (const float*)d_in[5];
    const float* bq         = (const float*)d_in[6];
    const int*   edge_index = (const int*)d_in[7];
    const int*   eids       = (const int*)d_in[8];
    float* out = (float*)d_out;

    float *sems, *query;
    int *deg, *bucket;
    uint4* bfrag;
    __nv_bfloat16 *x0h, *x0l, *x1h, *x1l, *aggh, *aggl;
    cudaGetSymbolAddress((void**)&sems,   g_sems);
    cudaGetSymbolAddress((void**)&query,  g_query);
    cudaGetSymbolAddress((void**)&deg,    g_deg);
    cudaGetSymbolAddress((void**)&bucket, g_bucket);
    cudaGetSymbolAddress((void**)&bfrag,  g_bfrag);
    cudaGetSymbolAddress((void**)&x0h,    g_x0h);
    cudaGetSymbolAddress((void**)&x0l,    g_x0l);
    cudaGetSymbolAddress((void**)&x1h,    g_x1h);
    cudaGetSymbolAddress((void**)&x1l,    g_x1l);
    cudaGetSymbolAddress((void**)&aggh,   g_aggh);
    cudaGetSymbolAddress((void**)&aggl,   g_aggl);

    cudaFuncSetAttribute(gemm_all,
                         cudaFuncAttributeMaxDynamicSharedMemorySize, GEMM_SMEM);

    const int edgeBlocks = (N_EDGES + 256 * CSR_EPT - 1) / (256 * CSR_EPT);
    const int agg0Blocks = (N_NODES * 32 + 255) / 256;
    const int agg1Blocks = (NREG * 32 + 255) / 256;
    const int gemm0Blocks = (N_NODES + 127) / 128;
    const int gemm1Blocks = (NREG + 127) / 128;

    dim3 gatherGrid((N_NODES * (D / 4) + 255) / 256, NP);
    dim3 wprepGrid(32, NP * NL);

    // phase 0: independent prep
    cudaMemsetAsync(deg, 0, (size_t)NP * N_NODES * sizeof(int));
    gather_all<<<gatherGrid, 256>>>(E, eids, x0h, x0l);
    csr_all<<<NP * edgeBlocks, 256>>>(edge_index, deg, bucket, edgeBlocks);
    wprep_all<<<wprepGrid, 256>>>(W_rel, W_root, bfrag);

    // layer 0 (full width)
    agg_all<<<NP * agg0Blocks, 256>>>(x0h, x0l, deg, bucket, aggh, aggl,
                                      N_NODES, agg0Blocks);
    gemm_all<<<NP * gemm0Blocks, 256, GEMM_SMEM>>>(
        aggh, aggl, x0h, x0l, bfrag, b,
        nullptr, x1h, x1l, N_NODES, 0, gemm0Blocks);

    // layer 1 (rows < NREG)
    agg_all<<<NP * agg1Blocks, 256>>>(x1h, x1l, deg, bucket, aggh, aggl,
                                      NREG, agg1Blocks);
    gemm_all<<<NP * gemm1Blocks, 256, GEMM_SMEM>>>(
        aggh, aggl, x1h, x1l, bfrag, b,
        sems, nullptr, nullptr, NREG, 1, gemm1Blocks);

    query_kernel<<<1, 128>>>(memb, Wq, bq, query);
    attn_kernel<<<(NREG + 7) / 8, 256>>>(sems, query, out);
}